// round 1
// baseline (speedup 1.0000x reference)
#include <cuda_runtime.h>
#include <math.h>

#define H_   16
#define T_   2048
#define DIM_ 2048
#define DK_  64
#define E2_  128                      // 2*DK
#define LAMBDA_INIT_ 0.6192834728526787f
#define OUT_SCALE_   0.3807165271473213f   // 1 - LAMBDA_INIT
#define EPS_ 1e-5f

// ---------------- scratch (global __device__ arrays; no allocations) --------
__device__ float g_q[H_*T_*E2_];
__device__ float g_k[H_*T_*E2_];
__device__ float g_v[H_*T_*E2_];
__device__ float g_att1[H_*T_*E2_];
__device__ float g_att2[H_*T_*E2_];
__device__ float g_lam[H_];

// ---------------- per-head lambda -------------------------------------------
__global__ void lam_kernel(const float* __restrict__ lq1, const float* __restrict__ lq2,
                           const float* __restrict__ lk1, const float* __restrict__ lk2) {
    int h = threadIdx.x;
    if (h < H_) {
        float d1 = 0.f, d2 = 0.f;
        for (int d = 0; d < DK_; d++) {
            d1 += lq1[h*DK_ + d] * lk1[h*DK_ + d];
            d2 += lq2[h*DK_ + d] * lk2[h*DK_ + d];
        }
        g_lam[h] = expf(d1) - expf(d2) + LAMBDA_INIT_;
    }
}

// ---------------- projection GEMM: Out[h][t][e] = sum_d X[t][d]*W[h][d][e] ---
// 64x64 tile, BK=16, 256 threads, 4x4 micro-tile.
__global__ void __launch_bounds__(256) proj_gemm(const float* __restrict__ X,
                                                 const float* __restrict__ W, int sel) {
    __shared__ float As[16][64];   // [k][t]  (transposed on store)
    __shared__ float Bs[16][64];   // [k][n]
    float* Out = sel == 0 ? g_q : (sel == 1 ? g_k : g_v);

    int tid = threadIdx.x;
    int tx = tid & 15, ty = tid >> 4;
    int row0 = blockIdx.x * 64;           // t tile
    int col0 = blockIdx.y * 64;           // n tile (n = h*128 + e)
    int h  = col0 >> 7;
    int e0 = col0 & 127;
    const float* Wp = W + (size_t)h * DIM_ * E2_ + e0;

    float acc[4][4] = {};
    int arow = tid >> 2, acol = (tid & 3) * 4;     // A loader: 64 rows x 16 cols
    int brow = tid >> 4, bcol = (tid & 15) * 4;    // B loader: 16 rows x 64 cols

    for (int k0 = 0; k0 < DIM_; k0 += 16) {
        float4 av = *(const float4*)(X  + (size_t)(row0 + arow) * DIM_ + k0 + acol);
        float4 bv = *(const float4*)(Wp + (size_t)(k0 + brow) * E2_ + bcol);
        As[acol + 0][arow] = av.x;
        As[acol + 1][arow] = av.y;
        As[acol + 2][arow] = av.z;
        As[acol + 3][arow] = av.w;
        *(float4*)&Bs[brow][bcol] = bv;
        __syncthreads();
        #pragma unroll
        for (int kk = 0; kk < 16; kk++) {
            float4 a4 = *(const float4*)&As[kk][ty * 4];
            float4 b4 = *(const float4*)&Bs[kk][tx * 4];
            float a[4] = {a4.x, a4.y, a4.z, a4.w};
            float b[4] = {b4.x, b4.y, b4.z, b4.w};
            #pragma unroll
            for (int i = 0; i < 4; i++)
                #pragma unroll
                for (int j = 0; j < 4; j++)
                    acc[i][j] = fmaf(a[i], b[j], acc[i][j]);
        }
        __syncthreads();
    }
    float* Op = Out + (size_t)h * T_ * E2_ + e0;
    #pragma unroll
    for (int i = 0; i < 4; i++) {
        float4 st = make_float4(acc[i][0], acc[i][1], acc[i][2], acc[i][3]);
        *(float4*)&Op[(size_t)(row0 + ty * 4 + i) * E2_ + tx * 4] = st;
    }
}

// ---------------- fix-up: recompute the 16 state rows with W_s --------------
// grid (h=16, z=3), 128 threads (one output col each), 16 accumulators.
__global__ void __launch_bounds__(128) proj_fix(const float* __restrict__ X,
                                                const float* __restrict__ Wqs,
                                                const float* __restrict__ Wks,
                                                const float* __restrict__ Wvs) {
    __shared__ float xs[512][16];   // [d-chunk][token]
    int h = blockIdx.x;
    int z = blockIdx.y;
    const float* Ws = z == 0 ? Wqs : (z == 1 ? Wks : Wvs);
    float* Out = z == 0 ? g_q : (z == 1 ? g_k : g_v);
    int e = threadIdx.x;
    const float* Wp = Ws + (size_t)h * DIM_ * E2_ + e;
    float acc[16] = {};

    for (int d0 = 0; d0 < DIM_; d0 += 512) {
        __syncthreads();
        for (int l = threadIdx.x; l < 16 * 512; l += 128) {
            int ti = l >> 9;
            int c  = l & 511;
            int t  = ti < 8 ? ti : 2032 + ti;    // 0..7 and 2040..2047
            xs[c][ti] = X[(size_t)t * DIM_ + d0 + c];
        }
        __syncthreads();
        for (int c = 0; c < 512; c++) {
            float w = Wp[(size_t)(d0 + c) * E2_];
            float4 x0 = *(const float4*)&xs[c][0];
            float4 x1 = *(const float4*)&xs[c][4];
            float4 x2 = *(const float4*)&xs[c][8];
            float4 x3 = *(const float4*)&xs[c][12];
            acc[0]  = fmaf(x0.x, w, acc[0]);   acc[1]  = fmaf(x0.y, w, acc[1]);
            acc[2]  = fmaf(x0.z, w, acc[2]);   acc[3]  = fmaf(x0.w, w, acc[3]);
            acc[4]  = fmaf(x1.x, w, acc[4]);   acc[5]  = fmaf(x1.y, w, acc[5]);
            acc[6]  = fmaf(x1.z, w, acc[6]);   acc[7]  = fmaf(x1.w, w, acc[7]);
            acc[8]  = fmaf(x2.x, w, acc[8]);   acc[9]  = fmaf(x2.y, w, acc[9]);
            acc[10] = fmaf(x2.z, w, acc[10]);  acc[11] = fmaf(x2.w, w, acc[11]);
            acc[12] = fmaf(x3.x, w, acc[12]);  acc[13] = fmaf(x3.y, w, acc[13]);
            acc[14] = fmaf(x3.z, w, acc[14]);  acc[15] = fmaf(x3.w, w, acc[15]);
        }
    }
    #pragma unroll
    for (int ti = 0; ti < 16; ti++) {
        int t = ti < 8 ? ti : 2032 + ti;
        Out[(size_t)h * T_ * E2_ + (size_t)t * E2_ + e] = acc[ti];
    }
}

// ---------------- flash attention (one stream per CTA) ----------------------
// grid (32 qblocks, 16 heads, 2 streams), 256 threads, ~83KB dyn smem.
__global__ void __launch_bounds__(256, 2) attn_kernel() {
    extern __shared__ float sm[];
    float* Qst = sm;                 // [d=64][i=64] stride 68 (d-major)
    float* Kst = Qst + 64 * 68;      // [d=64][j=64] stride 68
    float* Ps  = Kst + 64 * 68;      // [i=64][kk=64] stride 68
    float* Vs  = Ps + 64 * 68;       // [j=64][v=128]

    int tid = threadIdx.x;
    int tx = tid & 15, ty = tid >> 4;
    int qb = 31 - blockIdx.x;        // long blocks first
    int h = blockIdx.y;
    int which = blockIdx.z;
    int t0 = qb * 64;

    const float* Qg = g_q + ((size_t)h * T_ + t0) * E2_ + which * DK_;
    const float* Kg = g_k + (size_t)h * T_ * E2_ + which * DK_;
    const float* Vg = g_v + (size_t)h * T_ * E2_;
    float* Ao = (which ? g_att2 : g_att1) + ((size_t)h * T_ + t0) * E2_;

    // load Q tile (scaled by 1/sqrt(DK)=0.125), transposed to d-major
    #pragma unroll
    for (int r = 0; r < 4; r++) {
        int l = tid + r * 256;
        int i = l >> 4;
        int c = (l & 15) * 4;
        float4 v = *(const float4*)(Qg + (size_t)i * E2_ + c);
        Qst[(c + 0) * 68 + i] = v.x * 0.125f;
        Qst[(c + 1) * 68 + i] = v.y * 0.125f;
        Qst[(c + 2) * 68 + i] = v.z * 0.125f;
        Qst[(c + 3) * 68 + i] = v.w * 0.125f;
    }

    float o[4][8] = {};
    float m[4], lsum[4];
    #pragma unroll
    for (int i = 0; i < 4; i++) { m[i] = -INFINITY; lsum[i] = 0.f; }

    for (int kb = 0; kb <= qb; kb++) {
        __syncthreads();   // prev-iter PV reads (+ Q stores on iter 0) done
        const float* Kp = Kg + (size_t)kb * 64 * E2_;
        const float* Vp = Vg + (size_t)kb * 64 * E2_;
        #pragma unroll
        for (int r = 0; r < 4; r++) {
            int l = tid + r * 256;
            int j = l >> 4;
            int c = (l & 15) * 4;
            float4 v = *(const float4*)(Kp + (size_t)j * E2_ + c);
            Kst[(c + 0) * 68 + j] = v.x;
            Kst[(c + 1) * 68 + j] = v.y;
            Kst[(c + 2) * 68 + j] = v.z;
            Kst[(c + 3) * 68 + j] = v.w;
        }
        #pragma unroll
        for (int r = 0; r < 8; r++) {
            int l = tid + r * 256;
            int j = l >> 5;
            int c = (l & 31) * 4;
            *(float4*)(Vs + j * 128 + c) = *(const float4*)(Vp + (size_t)j * E2_ + c);
        }
        __syncthreads();

        // S = Q K^T (64x64), 4x4 per thread
        float s[4][4] = {};
        #pragma unroll 8
        for (int d = 0; d < 64; d++) {
            float4 a4 = *(const float4*)(Qst + d * 68 + ty * 4);
            float4 b4 = *(const float4*)(Kst + d * 68 + tx * 4);
            float a[4] = {a4.x, a4.y, a4.z, a4.w};
            float b[4] = {b4.x, b4.y, b4.z, b4.w};
            #pragma unroll
            for (int i = 0; i < 4; i++)
                #pragma unroll
                for (int j = 0; j < 4; j++)
                    s[i][j] = fmaf(a[i], b[j], s[i][j]);
        }
        if (kb == qb) {   // diagonal block: mask kj > qi
            #pragma unroll
            for (int i = 0; i < 4; i++)
                #pragma unroll
                for (int j = 0; j < 4; j++)
                    if (tx * 4 + j > ty * 4 + i) s[i][j] = -1e30f;
        }

        // online softmax (rows distributed over tx; reduce in 16-lane groups)
        #pragma unroll
        for (int i = 0; i < 4; i++) {
            float rm = fmaxf(fmaxf(s[i][0], s[i][1]), fmaxf(s[i][2], s[i][3]));
            #pragma unroll
            for (int off = 1; off < 16; off <<= 1)
                rm = fmaxf(rm, __shfl_xor_sync(0xffffffffu, rm, off));
            float nm = fmaxf(m[i], rm);
            float alpha = __expf(m[i] - nm);
            float rs = 0.f;
            #pragma unroll
            for (int j = 0; j < 4; j++) {
                s[i][j] = __expf(s[i][j] - nm);
                rs += s[i][j];
            }
            #pragma unroll
            for (int off = 1; off < 16; off <<= 1)
                rs += __shfl_xor_sync(0xffffffffu, rs, off);
            lsum[i] = lsum[i] * alpha + rs;
            m[i] = nm;
            #pragma unroll
            for (int jj = 0; jj < 8; jj++) o[i][jj] *= alpha;
            float4 pv = make_float4(s[i][0], s[i][1], s[i][2], s[i][3]);
            *(float4*)(Ps + (ty * 4 + i) * 68 + tx * 4) = pv;
        }
        __syncthreads();

        // O += P V  (64x64 @ 64x128), 4x8 per thread
        #pragma unroll 4
        for (int kk = 0; kk < 64; kk++) {
            float4 v0 = *(const float4*)(Vs + kk * 128 + tx * 8);
            float4 v1 = *(const float4*)(Vs + kk * 128 + tx * 8 + 4);
            #pragma unroll
            for (int i = 0; i < 4; i++) {
                float p = Ps[(ty * 4 + i) * 68 + kk];
                o[i][0] = fmaf(p, v0.x, o[i][0]);
                o[i][1] = fmaf(p, v0.y, o[i][1]);
                o[i][2] = fmaf(p, v0.z, o[i][2]);
                o[i][3] = fmaf(p, v0.w, o[i][3]);
                o[i][4] = fmaf(p, v1.x, o[i][4]);
                o[i][5] = fmaf(p, v1.y, o[i][5]);
                o[i][6] = fmaf(p, v1.z, o[i][6]);
                o[i][7] = fmaf(p, v1.w, o[i][7]);
            }
        }
    }

    #pragma unroll
    for (int i = 0; i < 4; i++) {
        float inv = 1.f / lsum[i];
        float4 r0 = make_float4(o[i][0]*inv, o[i][1]*inv, o[i][2]*inv, o[i][3]*inv);
        float4 r1 = make_float4(o[i][4]*inv, o[i][5]*inv, o[i][6]*inv, o[i][7]*inv);
        *(float4*)(Ao + (size_t)(ty * 4 + i) * E2_ + tx * 8)     = r0;
        *(float4*)(Ao + (size_t)(ty * 4 + i) * E2_ + tx * 8 + 4) = r1;
    }
}

// ---------------- combine + layernorm + scale -------------------------------
__global__ void __launch_bounds__(128) final_kernel(const float* __restrict__ gamma,
                                                    const float* __restrict__ beta,
                                                    float* __restrict__ Out) {
    int h = blockIdx.x >> 11;
    int t = blockIdx.x & 2047;
    int e = threadIdx.x;
    size_t base = ((size_t)h * T_ + t) * E2_;
    float a1 = g_att1[base + e];
    float a2 = g_att2[base + e];
    float v = a1 - g_lam[h] * a2;

    float s1 = v, s2 = v * v;
    #pragma unroll
    for (int off = 16; off; off >>= 1) {
        s1 += __shfl_xor_sync(0xffffffffu, s1, off);
        s2 += __shfl_xor_sync(0xffffffffu, s2, off);
    }
    __shared__ float red[8];
    int w = e >> 5, lane = e & 31;
    if (lane == 0) { red[w] = s1; red[4 + w] = s2; }
    __syncthreads();
    float sum = red[0] + red[1] + red[2] + red[3];
    float sq  = red[4] + red[5] + red[6] + red[7];
    float mu  = sum * (1.f / 128.f);
    float var = fmaxf(sq * (1.f / 128.f) - mu * mu, 0.f);
    float nv  = (v - mu) * rsqrtf(var + EPS_);
    Out[base + e] = (nv * gamma[h * E2_ + e] + beta[h * E2_ + e]) * OUT_SCALE_;
}

// ---------------- launch ----------------------------------------------------
extern "C" void kernel_launch(void* const* d_in, const int* in_sizes, int n_in,
                              void* d_out, int out_size) {
    const float* x   = (const float*)d_in[0];
    const float* Wq  = (const float*)d_in[1];
    const float* Wk  = (const float*)d_in[2];
    const float* Wv  = (const float*)d_in[3];
    const float* Wqs = (const float*)d_in[4];
    const float* Wks = (const float*)d_in[5];
    const float* Wvs = (const float*)d_in[6];
    const float* lq1 = (const float*)d_in[7];
    const float* lq2 = (const float*)d_in[8];
    const float* lk1 = (const float*)d_in[9];
    const float* lk2 = (const float*)d_in[10];
    const float* gam = (const float*)d_in[11];
    const float* bet = (const float*)d_in[12];
    float* out = (float*)d_out;

    size_t smem = (size_t)(3 * 64 * 68 + 64 * 128) * sizeof(float);  // 84992 B
    cudaFuncSetAttribute(attn_kernel, cudaFuncAttributeMaxDynamicSharedMemorySize, (int)smem);

    lam_kernel<<<1, 32>>>(lq1, lq2, lk1, lk2);
    dim3 gg(32, 32);
    proj_gemm<<<gg, 256>>>(x, Wq, 0);
    proj_gemm<<<gg, 256>>>(x, Wk, 1);
    proj_gemm<<<gg, 256>>>(x, Wv, 2);
    proj_fix<<<dim3(16, 3), 128>>>(x, Wqs, Wks, Wvs);
    attn_kernel<<<dim3(32, 16, 2), 256, smem>>>();
    final_kernel<<<32768, 128>>>(gam, bet, out);
}

// round 3
// speedup vs baseline: 1.3447x; 1.3447x over previous
#include <cuda_runtime.h>
#include <math.h>

#define H_   16
#define T_   2048
#define DIM_ 2048
#define DK_  64
#define E2_  128                      // 2*DK
#define LAMBDA_INIT_ 0.6192834728526787f
#define OUT_SCALE_   0.3807165271473213f   // 1 - LAMBDA_INIT
#define EPS_ 1e-5f

// ---------------- scratch (global __device__ arrays; no allocations) --------
__device__ float g_q[H_*T_*E2_];
__device__ float g_k[H_*T_*E2_];
__device__ float g_v[H_*T_*E2_];
__device__ float g_att1[H_*T_*E2_];
__device__ float g_att2[H_*T_*E2_];
__device__ float g_lam[H_];

// ---------------- per-head lambda -------------------------------------------
__global__ void lam_kernel(const float* __restrict__ lq1, const float* __restrict__ lq2,
                           const float* __restrict__ lk1, const float* __restrict__ lk2) {
    int h = threadIdx.x;
    if (h < H_) {
        float d1 = 0.f, d2 = 0.f;
        for (int d = 0; d < DK_; d++) {
            d1 += lq1[h*DK_ + d] * lk1[h*DK_ + d];
            d2 += lq2[h*DK_ + d] * lk2[h*DK_ + d];
        }
        g_lam[h] = expf(d1) - expf(d2) + LAMBDA_INIT_;
    }
}

// ---------------- projection GEMM (all 3 in one launch) ----------------------
// 128x128 tile, BK=8, 256 threads, 8x8 micro-tile, double buffered.
// Out[h][t][e] = sum_d X[t][d] * W[h][d][e]
__global__ void __launch_bounds__(256) proj_gemm3(const float* __restrict__ X,
                                                  const float* __restrict__ Wq,
                                                  const float* __restrict__ Wk,
                                                  const float* __restrict__ Wv) {
    __shared__ float As[2][8][132];   // [k][t], padded
    __shared__ float Bs[2][8][128];   // [k][e]
    int sel = blockIdx.z;
    const float* W = sel == 0 ? Wq : (sel == 1 ? Wk : Wv);
    float* Out = sel == 0 ? g_q : (sel == 1 ? g_k : g_v);

    int tid = threadIdx.x;
    int tx = tid & 15, ty = tid >> 4;
    int row0 = blockIdx.x * 128;
    int h = blockIdx.y;
    const float* Wp = W + (size_t)h * DIM_ * E2_;

    int ar = tid >> 1, ac = (tid & 1) * 4;     // A: 128 rows x 8 k
    int br = tid >> 5, bc = (tid & 31) * 4;    // B: 8 k x 128 cols
    const float* Ap = X + (size_t)(row0 + ar) * DIM_ + ac;
    const float* Bp = Wp + (size_t)br * E2_ + bc;

    float acc[8][8] = {};

    float4 av = *(const float4*)Ap;
    float4 bv = *(const float4*)Bp;
    As[0][ac+0][ar] = av.x; As[0][ac+1][ar] = av.y;
    As[0][ac+2][ar] = av.z; As[0][ac+3][ar] = av.w;
    *(float4*)&Bs[0][br][bc] = bv;
    __syncthreads();

    int buf = 0;
    for (int k0 = 8; k0 < DIM_; k0 += 8) {
        float4 an = *(const float4*)(Ap + k0);
        float4 bn = *(const float4*)(Bp + (size_t)k0 * E2_);
        #pragma unroll
        for (int kk = 0; kk < 8; kk++) {
            float4 a0 = *(const float4*)&As[buf][kk][ty * 4];
            float4 a1 = *(const float4*)&As[buf][kk][64 + ty * 4];
            float4 b0 = *(const float4*)&Bs[buf][kk][tx * 4];
            float4 b1 = *(const float4*)&Bs[buf][kk][64 + tx * 4];
            float a[8] = {a0.x,a0.y,a0.z,a0.w,a1.x,a1.y,a1.z,a1.w};
            float b[8] = {b0.x,b0.y,b0.z,b0.w,b1.x,b1.y,b1.z,b1.w};
            #pragma unroll
            for (int i = 0; i < 8; i++)
                #pragma unroll
                for (int j = 0; j < 8; j++)
                    acc[i][j] = fmaf(a[i], b[j], acc[i][j]);
        }
        buf ^= 1;
        As[buf][ac+0][ar] = an.x; As[buf][ac+1][ar] = an.y;
        As[buf][ac+2][ar] = an.z; As[buf][ac+3][ar] = an.w;
        *(float4*)&Bs[buf][br][bc] = bn;
        __syncthreads();
    }
    #pragma unroll
    for (int kk = 0; kk < 8; kk++) {
        float4 a0 = *(const float4*)&As[buf][kk][ty * 4];
        float4 a1 = *(const float4*)&As[buf][kk][64 + ty * 4];
        float4 b0 = *(const float4*)&Bs[buf][kk][tx * 4];
        float4 b1 = *(const float4*)&Bs[buf][kk][64 + tx * 4];
        float a[8] = {a0.x,a0.y,a0.z,a0.w,a1.x,a1.y,a1.z,a1.w};
        float b[8] = {b0.x,b0.y,b0.z,b0.w,b1.x,b1.y,b1.z,b1.w};
        #pragma unroll
        for (int i = 0; i < 8; i++)
            #pragma unroll
            for (int j = 0; j < 8; j++)
                acc[i][j] = fmaf(a[i], b[j], acc[i][j]);
    }

    float* Op = Out + (size_t)h * T_ * E2_;
    #pragma unroll
    for (int i = 0; i < 8; i++) {
        int r = (i < 4) ? (ty * 4 + i) : (64 + ty * 4 + i - 4);
        float4 c0 = make_float4(acc[i][0], acc[i][1], acc[i][2], acc[i][3]);
        float4 c1 = make_float4(acc[i][4], acc[i][5], acc[i][6], acc[i][7]);
        *(float4*)&Op[(size_t)(row0 + r) * E2_ + tx * 4]      = c0;
        *(float4*)&Op[(size_t)(row0 + r) * E2_ + 64 + tx * 4] = c1;
    }
}

// ---------------- fix-up: recompute the 16 state rows with W_s --------------
__global__ void __launch_bounds__(128) proj_fix(const float* __restrict__ X,
                                                const float* __restrict__ Wqs,
                                                const float* __restrict__ Wks,
                                                const float* __restrict__ Wvs) {
    __shared__ float xs[512][16];
    int h = blockIdx.x;
    int z = blockIdx.y;
    const float* Ws = z == 0 ? Wqs : (z == 1 ? Wks : Wvs);
    float* Out = z == 0 ? g_q : (z == 1 ? g_k : g_v);
    int e = threadIdx.x;
    const float* Wp = Ws + (size_t)h * DIM_ * E2_ + e;
    float acc[16] = {};

    for (int d0 = 0; d0 < DIM_; d0 += 512) {
        __syncthreads();
        for (int l = threadIdx.x; l < 16 * 512; l += 128) {
            int ti = l >> 9;
            int c  = l & 511;
            int t  = ti < 8 ? ti : 2032 + ti;
            xs[c][ti] = X[(size_t)t * DIM_ + d0 + c];
        }
        __syncthreads();
        for (int c = 0; c < 512; c++) {
            float w = Wp[(size_t)(d0 + c) * E2_];
            float4 x0 = *(const float4*)&xs[c][0];
            float4 x1 = *(const float4*)&xs[c][4];
            float4 x2 = *(const float4*)&xs[c][8];
            float4 x3 = *(const float4*)&xs[c][12];
            acc[0]  = fmaf(x0.x, w, acc[0]);   acc[1]  = fmaf(x0.y, w, acc[1]);
            acc[2]  = fmaf(x0.z, w, acc[2]);   acc[3]  = fmaf(x0.w, w, acc[3]);
            acc[4]  = fmaf(x1.x, w, acc[4]);   acc[5]  = fmaf(x1.y, w, acc[5]);
            acc[6]  = fmaf(x1.z, w, acc[6]);   acc[7]  = fmaf(x1.w, w, acc[7]);
            acc[8]  = fmaf(x2.x, w, acc[8]);   acc[9]  = fmaf(x2.y, w, acc[9]);
            acc[10] = fmaf(x2.z, w, acc[10]);  acc[11] = fmaf(x2.w, w, acc[11]);
            acc[12] = fmaf(x3.x, w, acc[12]);  acc[13] = fmaf(x3.y, w, acc[13]);
            acc[14] = fmaf(x3.z, w, acc[14]);  acc[15] = fmaf(x3.w, w, acc[15]);
        }
    }
    #pragma unroll
    for (int ti = 0; ti < 16; ti++) {
        int t = ti < 8 ? ti : 2032 + ti;
        Out[(size_t)h * T_ * E2_ + (size_t)t * E2_ + e] = acc[ti];
    }
}

// ---------------- flash attention: 128-row q-tile per CTA -------------------
// 1D grid of 512 = (16 qb) x (16 h) x (2 streams), longest blocks first.
__global__ void __launch_bounds__(256) attn_kernel() {
    extern __shared__ float sm[];
    float* Qst = sm;                  // [d=64][i=128] stride 132
    float* Kst = Qst + 64 * 132;      // [d=64][j=64]  stride 68
    float* Ps  = Kst + 64 * 68;       // [i=128][kk=64] stride 68
    float* Vs  = Ps + 128 * 68;       // [j=64][v=128]

    int tid = threadIdx.x;
    int tx = tid & 15, ty = tid >> 4;
    int bid = (int)blockIdx.x;
    int qb = 15 - (bid >> 5);         // long blocks first
    int rem = bid & 31;
    int h = rem >> 1;
    int which = rem & 1;
    int t0 = qb * 128;

    const float* Qg = g_q + ((size_t)h * T_ + t0) * E2_ + which * DK_;
    const float* Kg = g_k + (size_t)h * T_ * E2_ + which * DK_;
    const float* Vg = g_v + (size_t)h * T_ * E2_;
    float* Ao = (which ? g_att2 : g_att1) + ((size_t)h * T_ + t0) * E2_;

    // rows owned by this thread
    int rrow[8];
    #pragma unroll
    for (int i = 0; i < 8; i++) rrow[i] = (i < 4) ? (ty * 4 + i) : (64 + ty * 4 + i - 4);

    // load Q tile 128x64 -> Qst[d][i] (scaled), conflict-free (i in lane)
    {
        int i = tid & 127;
        int cbase = (tid >> 7) * 4;
        #pragma unroll
        for (int r = 0; r < 8; r++) {
            int c = cbase + r * 8;
            float4 v = *(const float4*)(Qg + (size_t)i * E2_ + c);
            Qst[(c + 0) * 132 + i] = v.x * 0.125f;
            Qst[(c + 1) * 132 + i] = v.y * 0.125f;
            Qst[(c + 2) * 132 + i] = v.z * 0.125f;
            Qst[(c + 3) * 132 + i] = v.w * 0.125f;
        }
    }

    float o[8][8] = {};
    float m[8], lsum[8];
    #pragma unroll
    for (int i = 0; i < 8; i++) { m[i] = -INFINITY; lsum[i] = 0.f; }

    int nkb = 2 * qb + 2;
    for (int kb = 0; kb < nkb; kb++) {
        __syncthreads();   // prior PV reads (and Q store on iter 0) complete
        const float* Kp = Kg + (size_t)kb * 64 * E2_;
        const float* Vp = Vg + (size_t)kb * 64 * E2_;
        // K tile 64x64 -> Kst[d][j] (j in lane: conflict-free stores)
        {
            int j = tid & 63;
            int cbase = (tid >> 6) * 4;
            #pragma unroll
            for (int r = 0; r < 4; r++) {
                int c = cbase + r * 16;
                float4 v = *(const float4*)(Kp + (size_t)j * E2_ + c);
                Kst[(c + 0) * 68 + j] = v.x;
                Kst[(c + 1) * 68 + j] = v.y;
                Kst[(c + 2) * 68 + j] = v.z;
                Kst[(c + 3) * 68 + j] = v.w;
            }
        }
        // V tile 64x128 row-major
        #pragma unroll
        for (int r = 0; r < 8; r++) {
            int l = tid + r * 256;
            int j = l >> 5;
            int c = (l & 31) * 4;
            *(float4*)(Vs + j * 128 + c) = *(const float4*)(Vp + (size_t)j * E2_ + c);
        }
        __syncthreads();

        // S = Q K^T : 128x64, 8x4 per thread
        float s[8][4] = {};
        #pragma unroll 4
        for (int d = 0; d < 64; d++) {
            float4 a0 = *(const float4*)(Qst + d * 132 + ty * 4);
            float4 a1 = *(const float4*)(Qst + d * 132 + 64 + ty * 4);
            float4 b4 = *(const float4*)(Kst + d * 68 + tx * 4);
            float a[8] = {a0.x,a0.y,a0.z,a0.w,a1.x,a1.y,a1.z,a1.w};
            float b[4] = {b4.x,b4.y,b4.z,b4.w};
            #pragma unroll
            for (int i = 0; i < 8; i++)
                #pragma unroll
                for (int j = 0; j < 4; j++)
                    s[i][j] = fmaf(a[i], b[j], s[i][j]);
        }
        if (kb >= 2 * qb) {            // last two tiles need causal mask
            int coff = (kb - 2 * qb) * 64;
            #pragma unroll
            for (int i = 0; i < 8; i++)
                #pragma unroll
                for (int j = 0; j < 4; j++)
                    if (coff + tx * 4 + j > rrow[i]) s[i][j] = -1e30f;
        }

        // online softmax; rows reduced over the 16-lane tx group
        #pragma unroll
        for (int i = 0; i < 8; i++) {
            float rm = fmaxf(fmaxf(s[i][0], s[i][1]), fmaxf(s[i][2], s[i][3]));
            #pragma unroll
            for (int off = 1; off < 16; off <<= 1)
                rm = fmaxf(rm, __shfl_xor_sync(0xffffffffu, rm, off));
            float nm = fmaxf(m[i], rm);
            float alpha = __expf(m[i] - nm);
            float rs = 0.f;
            #pragma unroll
            for (int j = 0; j < 4; j++) {
                s[i][j] = __expf(s[i][j] - nm);
                rs += s[i][j];
            }
            #pragma unroll
            for (int off = 1; off < 16; off <<= 1)
                rs += __shfl_xor_sync(0xffffffffu, rs, off);
            lsum[i] = lsum[i] * alpha + rs;
            m[i] = nm;
            #pragma unroll
            for (int jj = 0; jj < 8; jj++) o[i][jj] *= alpha;
            *(float4*)(Ps + rrow[i] * 68 + tx * 4) =
                make_float4(s[i][0], s[i][1], s[i][2], s[i][3]);
        }
        __syncthreads();

        // O += P V : 128x128 += (128x64)(64x128), kk stepped by 4
        #pragma unroll 2
        for (int kk0 = 0; kk0 < 64; kk0 += 4) {
            float4 v0[4], v1[4];
            #pragma unroll
            for (int q = 0; q < 4; q++) {
                v0[q] = *(const float4*)(Vs + (kk0 + q) * 128 + tx * 4);
                v1[q] = *(const float4*)(Vs + (kk0 + q) * 128 + 64 + tx * 4);
            }
            #pragma unroll
            for (int i = 0; i < 8; i++) {
                float4 p = *(const float4*)(Ps + rrow[i] * 68 + kk0);
                float pp[4] = {p.x, p.y, p.z, p.w};
                #pragma unroll
                for (int q = 0; q < 4; q++) {
                    o[i][0] = fmaf(pp[q], v0[q].x, o[i][0]);
                    o[i][1] = fmaf(pp[q], v0[q].y, o[i][1]);
                    o[i][2] = fmaf(pp[q], v0[q].z, o[i][2]);
                    o[i][3] = fmaf(pp[q], v0[q].w, o[i][3]);
                    o[i][4] = fmaf(pp[q], v1[q].x, o[i][4]);
                    o[i][5] = fmaf(pp[q], v1[q].y, o[i][5]);
                    o[i][6] = fmaf(pp[q], v1[q].z, o[i][6]);
                    o[i][7] = fmaf(pp[q], v1[q].w, o[i][7]);
                }
            }
        }
    }

    #pragma unroll
    for (int i = 0; i < 8; i++) {
        float inv = 1.f / lsum[i];
        float4 r0 = make_float4(o[i][0]*inv, o[i][1]*inv, o[i][2]*inv, o[i][3]*inv);
        float4 r1 = make_float4(o[i][4]*inv, o[i][5]*inv, o[i][6]*inv, o[i][7]*inv);
        *(float4*)(Ao + (size_t)rrow[i] * E2_ + tx * 4)      = r0;
        *(float4*)(Ao + (size_t)rrow[i] * E2_ + 64 + tx * 4) = r1;
    }
}

// ---------------- combine + layernorm + scale -------------------------------
__global__ void __launch_bounds__(128) final_kernel(const float* __restrict__ gamma,
                                                    const float* __restrict__ beta,
                                                    float* __restrict__ Out) {
    int h = blockIdx.x >> 11;
    int t = blockIdx.x & 2047;
    int e = threadIdx.x;
    size_t base = ((size_t)h * T_ + t) * E2_;
    float a1 = g_att1[base + e];
    float a2 = g_att2[base + e];
    float v = a1 - g_lam[h] * a2;

    float s1 = v, s2 = v * v;
    #pragma unroll
    for (int off = 16; off; off >>= 1) {
        s1 += __shfl_xor_sync(0xffffffffu, s1, off);
        s2 += __shfl_xor_sync(0xffffffffu, s2, off);
    }
    __shared__ float red[8];
    int w = e >> 5, lane = e & 31;
    if (lane == 0) { red[w] = s1; red[4 + w] = s2; }
    __syncthreads();
    float sum = red[0] + red[1] + red[2] + red[3];
    float sq  = red[4] + red[5] + red[6] + red[7];
    float mu  = sum * (1.f / 128.f);
    float var = fmaxf(sq * (1.f / 128.f) - mu * mu, 0.f);
    float nv  = (v - mu) * rsqrtf(var + EPS_);
    Out[base + e] = (nv * gamma[h * E2_ + e] + beta[h * E2_ + e]) * OUT_SCALE_;
}

// ---------------- launch ----------------------------------------------------
extern "C" void kernel_launch(void* const* d_in, const int* in_sizes, int n_in,
                              void* d_out, int out_size) {
    const float* x   = (const float*)d_in[0];
    const float* Wq  = (const float*)d_in[1];
    const float* Wk  = (const float*)d_in[2];
    const float* Wv  = (const float*)d_in[3];
    const float* Wqs = (const float*)d_in[4];
    const float* Wks = (const float*)d_in[5];
    const float* Wvs = (const float*)d_in[6];
    const float* lq1 = (const float*)d_in[7];
    const float* lq2 = (const float*)d_in[8];
    const float* lk1 = (const float*)d_in[9];
    const float* lk2 = (const float*)d_in[10];
    const float* gam = (const float*)d_in[11];
    const float* bet = (const float*)d_in[12];
    float* out = (float*)d_out;

    size_t smem = (size_t)(64*132 + 64*68 + 128*68 + 64*128) * sizeof(float);  // 118784
    cudaFuncSetAttribute(attn_kernel, cudaFuncAttributeMaxDynamicSharedMemorySize, (int)smem);

    lam_kernel<<<1, 32>>>(lq1, lq2, lk1, lk2);
    proj_gemm3<<<dim3(16, 16, 3), 256>>>(x, Wq, Wk, Wv);
    proj_fix<<<dim3(16, 3), 128>>>(x, Wqs, Wks, Wvs);
    attn_kernel<<<512, 256, smem>>>();
    final_kernel<<<32768, 128>>>(gam, bet, out);
}

// round 5
// speedup vs baseline: 1.7840x; 1.3267x over previous
#include <cuda_runtime.h>
#include <cuda_fp16.h>
#include <math.h>
#include <cstdint>

#define H_   16
#define T_   2048
#define DIM_ 2048
#define DK_  64
#define E2_  128
#define LAMBDA_INIT_ 0.6192834728526787f
#define OUT_SCALE_   0.3807165271473213f
#define EPS_ 1e-5f

// ---------------- scratch ----------------------------------------------------
__device__ float g_q[H_*T_*E2_];
__device__ float g_k[H_*T_*E2_];
__device__ float g_v[H_*T_*E2_];
__device__ float g_att1[H_*T_*E2_];
__device__ float g_att2[H_*T_*E2_];
__device__ float g_lam[H_];
__device__ __align__(256) __half g_xhi[T_*DIM_];
__device__ __align__(256) __half g_xlo[T_*DIM_];
__device__ __align__(256) __half g_wthi[3*H_*E2_*DIM_];   // [sel][h][e][d]
__device__ __align__(256) __half g_wtlo[3*H_*E2_*DIM_];

// ---------------- helpers ----------------------------------------------------
__device__ __forceinline__ uint32_t smem_to_u32(const void* p) {
    uint32_t a;
    asm("{ .reg .u64 t; cvta.to.shared.u64 t, %1; cvt.u32.u64 %0, t; }" : "=r"(a) : "l"(p));
    return a;
}
#define LDSM4(r, addr) \
    asm volatile("ldmatrix.sync.aligned.m8n8.x4.shared.b16 {%0,%1,%2,%3}, [%4];" \
        : "=r"((r)[0]), "=r"((r)[1]), "=r"((r)[2]), "=r"((r)[3]) : "r"(addr))
#define MMA16816(c, a, b) \
    asm volatile("mma.sync.aligned.m16n8k16.row.col.f32.f16.f16.f32 " \
        "{%0,%1,%2,%3}, {%4,%5,%6,%7}, {%8,%9}, {%0,%1,%2,%3};" \
        : "+f"((c)[0]), "+f"((c)[1]), "+f"((c)[2]), "+f"((c)[3]) \
        : "r"((a)[0]), "r"((a)[1]), "r"((a)[2]), "r"((a)[3]), "r"((b)[0]), "r"((b)[1]))
#define CP_ASYNC16(sa, ga) \
    asm volatile("cp.async.cg.shared.global [%0], [%1], 16;" :: "r"(sa), "l"(ga))
#define CP_COMMIT() asm volatile("cp.async.commit_group;" ::: "memory")

// ---------------- lambda -----------------------------------------------------
__global__ void lam_kernel(const float* __restrict__ lq1, const float* __restrict__ lq2,
                           const float* __restrict__ lk1, const float* __restrict__ lk2) {
    int h = threadIdx.x;
    if (h < H_) {
        float d1 = 0.f, d2 = 0.f;
        for (int d = 0; d < DK_; d++) {
            d1 += lq1[h*DK_ + d] * lk1[h*DK_ + d];
            d2 += lq2[h*DK_ + d] * lk2[h*DK_ + d];
        }
        g_lam[h] = expf(d1) - expf(d2) + LAMBDA_INIT_;
    }
}

// ---------------- prep: split X into fp16 hi/lo ------------------------------
__global__ void __launch_bounds__(256) split_x(const float* __restrict__ X) {
    int t = blockIdx.x;
    const float* xp = X + (size_t)t * DIM_;
    __half* hp = g_xhi + (size_t)t * DIM_;
    __half* lp = g_xlo + (size_t)t * DIM_;
    for (int j = threadIdx.x; j < DIM_; j += 256) {
        float v = xp[j];
        __half hi = __float2half_rn(v);
        hp[j] = hi;
        lp[j] = __float2half_rn(v - __half2float(hi));
    }
}

// ---------------- prep: transpose + split W ----------------------------------
// W[h][d][e] fp32 -> WT[sel*16+h][e][d] fp16 hi/lo. 32x32 tiles.
__global__ void __launch_bounds__(256) transp_w(const float* __restrict__ Wq,
                                                const float* __restrict__ Wk,
                                                const float* __restrict__ Wv) {
    __shared__ float tile[32][33];
    int hs = blockIdx.z;
    int sel = hs >> 4, h = hs & 15;
    const float* W = sel == 0 ? Wq : (sel == 1 ? Wk : Wv);
    int d0 = blockIdx.x * 32;
    int e0 = blockIdx.y * 32;
    int tx = threadIdx.x & 31, ty = threadIdx.x >> 5;
    #pragma unroll
    for (int i = 0; i < 4; i++) {
        int d = d0 + ty + i * 8;
        tile[ty + i * 8][tx] = W[((size_t)h * DIM_ + d) * E2_ + e0 + tx];
    }
    __syncthreads();
    #pragma unroll
    for (int i = 0; i < 4; i++) {
        int e = e0 + ty + i * 8;
        float v = tile[tx][ty + i * 8];
        __half hi = __float2half_rn(v);
        size_t idx = ((size_t)hs * E2_ + e) * DIM_ + d0 + tx;
        g_wthi[idx] = hi;
        g_wtlo[idx] = __float2half_rn(v - __half2float(hi));
    }
}

// ---------------- projection via mma.sync split-fp16 -------------------------
// grid (16 tblk, 16 h, 3 sel), 256 threads, 144KB dyn smem.
// C[128t x 128e] = Xhi*Whi + Xhi*Wlo + Xlo*Whi (fp32 accum)
#define PRJ_ROWB   144          // bytes per smem row (128 data + 16 pad)
#define PRJ_TILEB  (128*PRJ_ROWB)      // 18432
#define PRJ_STAGEB (4*PRJ_TILEB)       // 73728

__global__ void __launch_bounds__(256) proj_mma() {
    extern __shared__ char smc[];
    uint32_t sbase = smem_to_u32(smc);
    int tid = threadIdx.x, lane = tid & 31, wid = tid >> 5;
    int tblk = blockIdx.x, h = blockIdx.y, sel = blockIdx.z;
    int row0 = tblk * 128;

    const char* gA0 = (const char*)g_xhi + (size_t)row0 * (DIM_ * 2);
    const char* gA1 = (const char*)g_xlo + (size_t)row0 * (DIM_ * 2);
    size_t wofs = (size_t)(sel * H_ + h) * E2_ * (DIM_ * 2);
    const char* gA2 = (const char*)g_wthi + wofs;
    const char* gA3 = (const char*)g_wtlo + wofs;

    int m0 = (wid >> 1) * 32, n0 = (wid & 1) * 64;
    float acc[2][8][4] = {};

    // issue one K-stage (64 k) into buffer b
    auto issue = [&](int s, int b) {
        uint32_t sb = sbase + b * PRJ_STAGEB;
        size_t k0b = (size_t)s * 128;              // 64 halves = 128 bytes
        #pragma unroll
        for (int i = 0; i < 4; i++) {
            int l = tid + i * 256;
            int row = l >> 3, seg = l & 7;
            size_t gofs = (size_t)row * (DIM_ * 2) + k0b + seg * 16;
            uint32_t sofs = row * PRJ_ROWB + seg * 16;
            CP_ASYNC16(sb + 0 * PRJ_TILEB + sofs, gA0 + gofs);
            CP_ASYNC16(sb + 1 * PRJ_TILEB + sofs, gA1 + gofs);
            CP_ASYNC16(sb + 2 * PRJ_TILEB + sofs, gA2 + gofs);
            CP_ASYNC16(sb + 3 * PRJ_TILEB + sofs, gA3 + gofs);
        }
        CP_COMMIT();
    };

    issue(0, 0);
    for (int s = 0; s < 32; s++) {
        int b = s & 1;
        if (s < 31) issue(s + 1, b ^ 1);
        if (s < 31) asm volatile("cp.async.wait_group 1;" ::: "memory");
        else        asm volatile("cp.async.wait_group 0;" ::: "memory");
        __syncthreads();

        uint32_t sAh = sbase + b * PRJ_STAGEB;
        uint32_t sAl = sAh + PRJ_TILEB;
        uint32_t sBh = sAl + PRJ_TILEB;
        uint32_t sBl = sBh + PRJ_TILEB;
        #pragma unroll
        for (int kk = 0; kk < 64; kk += 16) {
            uint32_t ah[2][4], al[2][4];
            #pragma unroll
            for (int mt = 0; mt < 2; mt++) {
                uint32_t off = (uint32_t)(m0 + mt * 16 + (lane & 15)) * PRJ_ROWB
                             + (kk + (lane >> 4) * 8) * 2;
                LDSM4(ah[mt], sAh + off);
                LDSM4(al[mt], sAl + off);
            }
            uint32_t bh[4][4], bl[4][4];
            #pragma unroll
            for (int np = 0; np < 4; np++) {
                uint32_t off = (uint32_t)(n0 + np * 16 + (lane & 7) + ((lane >> 4) & 1) * 8) * PRJ_ROWB
                             + (kk + ((lane >> 3) & 1) * 8) * 2;
                LDSM4(bh[np], sBh + off);
                LDSM4(bl[np], sBl + off);
            }
            #pragma unroll
            for (int mt = 0; mt < 2; mt++)
                #pragma unroll
                for (int nt = 0; nt < 8; nt++) {
                    uint32_t* bhp = &bh[nt >> 1][(nt & 1) * 2];
                    uint32_t* blp = &bl[nt >> 1][(nt & 1) * 2];
                    MMA16816(acc[mt][nt], ah[mt], bhp);
                    MMA16816(acc[mt][nt], ah[mt], blp);
                    MMA16816(acc[mt][nt], al[mt], bhp);
                }
        }
        __syncthreads();
    }

    float* Out = (sel == 0 ? g_q : (sel == 1 ? g_k : g_v)) + (size_t)h * T_ * E2_;
    #pragma unroll
    for (int mt = 0; mt < 2; mt++)
        #pragma unroll
        for (int nt = 0; nt < 8; nt++) {
            int r = row0 + m0 + mt * 16 + (lane >> 2);
            int c = n0 + nt * 8 + (lane & 3) * 2;
            *(float2*)&Out[(size_t)r * E2_ + c] = make_float2(acc[mt][nt][0], acc[mt][nt][1]);
            *(float2*)&Out[(size_t)(r + 8) * E2_ + c] = make_float2(acc[mt][nt][2], acc[mt][nt][3]);
        }
}

// ---------------- fix-up: recompute 16 state rows with W_s (fp32) ------------
__global__ void __launch_bounds__(128) proj_fix(const float* __restrict__ X,
                                                const float* __restrict__ Wqs,
                                                const float* __restrict__ Wks,
                                                const float* __restrict__ Wvs) {
    __shared__ float xs[512][16];
    int h = blockIdx.x;
    int z = blockIdx.y;
    const float* Ws = z == 0 ? Wqs : (z == 1 ? Wks : Wvs);
    float* Out = z == 0 ? g_q : (z == 1 ? g_k : g_v);
    int e = threadIdx.x;
    const float* Wp = Ws + (size_t)h * DIM_ * E2_ + e;
    float acc[16] = {};
    for (int d0 = 0; d0 < DIM_; d0 += 512) {
        __syncthreads();
        for (int l = threadIdx.x; l < 16 * 512; l += 128) {
            int ti = l >> 9;
            int c  = l & 511;
            int t  = ti < 8 ? ti : 2032 + ti;
            xs[c][ti] = X[(size_t)t * DIM_ + d0 + c];
        }
        __syncthreads();
        for (int c = 0; c < 512; c++) {
            float w = Wp[(size_t)(d0 + c) * E2_];
            float4 x0 = *(const float4*)&xs[c][0];
            float4 x1 = *(const float4*)&xs[c][4];
            float4 x2 = *(const float4*)&xs[c][8];
            float4 x3 = *(const float4*)&xs[c][12];
            acc[0]  = fmaf(x0.x, w, acc[0]);   acc[1]  = fmaf(x0.y, w, acc[1]);
            acc[2]  = fmaf(x0.z, w, acc[2]);   acc[3]  = fmaf(x0.w, w, acc[3]);
            acc[4]  = fmaf(x1.x, w, acc[4]);   acc[5]  = fmaf(x1.y, w, acc[5]);
            acc[6]  = fmaf(x1.z, w, acc[6]);   acc[7]  = fmaf(x1.w, w, acc[7]);
            acc[8]  = fmaf(x2.x, w, acc[8]);   acc[9]  = fmaf(x2.y, w, acc[9]);
            acc[10] = fmaf(x2.z, w, acc[10]);  acc[11] = fmaf(x2.w, w, acc[11]);
            acc[12] = fmaf(x3.x, w, acc[12]);  acc[13] = fmaf(x3.y, w, acc[13]);
            acc[14] = fmaf(x3.z, w, acc[14]);  acc[15] = fmaf(x3.w, w, acc[15]);
        }
    }
    #pragma unroll
    for (int ti = 0; ti < 16; ti++) {
        int t = ti < 8 ? ti : 2032 + ti;
        Out[(size_t)h * T_ * E2_ + (size_t)t * E2_ + e] = acc[ti];
    }
}

// ---------------- flash attention (unchanged, fp32 SIMT) ---------------------
__global__ void __launch_bounds__(256) attn_kernel() {
    extern __shared__ float sm[];
    float* Qst = sm;
    float* Kst = Qst + 64 * 132;
    float* Ps  = Kst + 64 * 68;
    float* Vs  = Ps + 128 * 68;

    int tid = threadIdx.x;
    int tx = tid & 15, ty = tid >> 4;
    int bid = (int)blockIdx.x;
    int qb = 15 - (bid >> 5);
    int rem = bid & 31;
    int h = rem >> 1;
    int which = rem & 1;
    int t0 = qb * 128;

    const float* Qg = g_q + ((size_t)h * T_ + t0) * E2_ + which * DK_;
    const float* Kg = g_k + (size_t)h * T_ * E2_ + which * DK_;
    const float* Vg = g_v + (size_t)h * T_ * E2_;
    float* Ao = (which ? g_att2 : g_att1) + ((size_t)h * T_ + t0) * E2_;

    int rrow[8];
    #pragma unroll
    for (int i = 0; i < 8; i++) rrow[i] = (i < 4) ? (ty * 4 + i) : (64 + ty * 4 + i - 4);

    {
        int i = tid & 127;
        int cbase = (tid >> 7) * 4;
        #pragma unroll
        for (int r = 0; r < 8; r++) {
            int c = cbase + r * 8;
            float4 v = *(const float4*)(Qg + (size_t)i * E2_ + c);
            Qst[(c + 0) * 132 + i] = v.x * 0.125f;
            Qst[(c + 1) * 132 + i] = v.y * 0.125f;
            Qst[(c + 2) * 132 + i] = v.z * 0.125f;
            Qst[(c + 3) * 132 + i] = v.w * 0.125f;
        }
    }

    float o[8][8] = {};
    float m[8], lsum[8];
    #pragma unroll
    for (int i = 0; i < 8; i++) { m[i] = -INFINITY; lsum[i] = 0.f; }

    int nkb = 2 * qb + 2;
    for (int kb = 0; kb < nkb; kb++) {
        __syncthreads();
        const float* Kp = Kg + (size_t)kb * 64 * E2_;
        const float* Vp = Vg + (size_t)kb * 64 * E2_;
        {
            int j = tid & 63;
            int cbase = (tid >> 6) * 4;
            #pragma unroll
            for (int r = 0; r < 4; r++) {
                int c = cbase + r * 16;
                float4 v = *(const float4*)(Kp + (size_t)j * E2_ + c);
                Kst[(c + 0) * 68 + j] = v.x;
                Kst[(c + 1) * 68 + j] = v.y;
                Kst[(c + 2) * 68 + j] = v.z;
                Kst[(c + 3) * 68 + j] = v.w;
            }
        }
        #pragma unroll
        for (int r = 0; r < 8; r++) {
            int l = tid + r * 256;
            int j = l >> 5;
            int c = (l & 31) * 4;
            *(float4*)(Vs + j * 128 + c) = *(const float4*)(Vp + (size_t)j * E2_ + c);
        }
        __syncthreads();

        float s[8][4] = {};
        #pragma unroll 4
        for (int d = 0; d < 64; d++) {
            float4 a0 = *(const float4*)(Qst + d * 132 + ty * 4);
            float4 a1 = *(const float4*)(Qst + d * 132 + 64 + ty * 4);
            float4 b4 = *(const float4*)(Kst + d * 68 + tx * 4);
            float a[8] = {a0.x,a0.y,a0.z,a0.w,a1.x,a1.y,a1.z,a1.w};
            float b[4] = {b4.x,b4.y,b4.z,b4.w};
            #pragma unroll
            for (int i = 0; i < 8; i++)
                #pragma unroll
                for (int j = 0; j < 4; j++)
                    s[i][j] = fmaf(a[i], b[j], s[i][j]);
        }
        if (kb >= 2 * qb) {
            int coff = (kb - 2 * qb) * 64;
            #pragma unroll
            for (int i = 0; i < 8; i++)
                #pragma unroll
                for (int j = 0; j < 4; j++)
                    if (coff + tx * 4 + j > rrow[i]) s[i][j] = -1e30f;
        }

        #pragma unroll
        for (int i = 0; i < 8; i++) {
            float rm = fmaxf(fmaxf(s[i][0], s[i][1]), fmaxf(s[i][2], s[i][3]));
            #pragma unroll
            for (int off = 1; off < 16; off <<= 1)
                rm = fmaxf(rm, __shfl_xor_sync(0xffffffffu, rm, off));
            float nm = fmaxf(m[i], rm);
            float alpha = __expf(m[i] - nm);
            float rs = 0.f;
            #pragma unroll
            for (int j = 0; j < 4; j++) {
                s[i][j] = __expf(s[i][j] - nm);
                rs += s[i][j];
            }
            #pragma unroll
            for (int off = 1; off < 16; off <<= 1)
                rs += __shfl_xor_sync(0xffffffffu, rs, off);
            lsum[i] = lsum[i] * alpha + rs;
            m[i] = nm;
            #pragma unroll
            for (int jj = 0; jj < 8; jj++) o[i][jj] *= alpha;
            *(float4*)(Ps + rrow[i] * 68 + tx * 4) =
                make_float4(s[i][0], s[i][1], s[i][2], s[i][3]);
        }
        __syncthreads();

        #pragma unroll 2
        for (int kk0 = 0; kk0 < 64; kk0 += 4) {
            float4 v0[4], v1[4];
            #pragma unroll
            for (int q = 0; q < 4; q++) {
                v0[q] = *(const float4*)(Vs + (kk0 + q) * 128 + tx * 4);
                v1[q] = *(const float4*)(Vs + (kk0 + q) * 128 + 64 + tx * 4);
            }
            #pragma unroll
            for (int i = 0; i < 8; i++) {
                float4 p = *(const float4*)(Ps + rrow[i] * 68 + kk0);
                float pp[4] = {p.x, p.y, p.z, p.w};
                #pragma unroll
                for (int q = 0; q < 4; q++) {
                    o[i][0] = fmaf(pp[q], v0[q].x, o[i][0]);
                    o[i][1] = fmaf(pp[q], v0[q].y, o[i][1]);
                    o[i][2] = fmaf(pp[q], v0[q].z, o[i][2]);
                    o[i][3] = fmaf(pp[q], v0[q].w, o[i][3]);
                    o[i][4] = fmaf(pp[q], v1[q].x, o[i][4]);
                    o[i][5] = fmaf(pp[q], v1[q].y, o[i][5]);
                    o[i][6] = fmaf(pp[q], v1[q].z, o[i][6]);
                    o[i][7] = fmaf(pp[q], v1[q].w, o[i][7]);
                }
            }
        }
    }

    #pragma unroll
    for (int i = 0; i < 8; i++) {
        float inv = 1.f / lsum[i];
        float4 r0 = make_float4(o[i][0]*inv, o[i][1]*inv, o[i][2]*inv, o[i][3]*inv);
        float4 r1 = make_float4(o[i][4]*inv, o[i][5]*inv, o[i][6]*inv, o[i][7]*inv);
        *(float4*)(Ao + (size_t)rrow[i] * E2_ + tx * 4)      = r0;
        *(float4*)(Ao + (size_t)rrow[i] * E2_ + 64 + tx * 4) = r1;
    }
}

// ---------------- combine + layernorm + scale --------------------------------
__global__ void __launch_bounds__(128) final_kernel(const float* __restrict__ gamma,
                                                    const float* __restrict__ beta,
                                                    float* __restrict__ Out) {
    int h = blockIdx.x >> 11;
    int t = blockIdx.x & 2047;
    int e = threadIdx.x;
    size_t base = ((size_t)h * T_ + t) * E2_;
    float a1 = g_att1[base + e];
    float a2 = g_att2[base + e];
    float v = a1 - g_lam[h] * a2;

    float s1 = v, s2 = v * v;
    #pragma unroll
    for (int off = 16; off; off >>= 1) {
        s1 += __shfl_xor_sync(0xffffffffu, s1, off);
        s2 += __shfl_xor_sync(0xffffffffu, s2, off);
    }
    __shared__ float red[8];
    int w = e >> 5, lane = e & 31;
    if (lane == 0) { red[w] = s1; red[4 + w] = s2; }
    __syncthreads();
    float sum = red[0] + red[1] + red[2] + red[3];
    float sq  = red[4] + red[5] + red[6] + red[7];
    float mu  = sum * (1.f / 128.f);
    float var = fmaxf(sq * (1.f / 128.f) - mu * mu, 0.f);
    float nv  = (v - mu) * rsqrtf(var + EPS_);
    Out[base + e] = (nv * gamma[h * E2_ + e] + beta[h * E2_ + e]) * OUT_SCALE_;
}

// ---------------- launch -----------------------------------------------------
extern "C" void kernel_launch(void* const* d_in, const int* in_sizes, int n_in,
                              void* d_out, int out_size) {
    const float* x   = (const float*)d_in[0];
    const float* Wq  = (const float*)d_in[1];
    const float* Wk  = (const float*)d_in[2];
    const float* Wv  = (const float*)d_in[3];
    const float* Wqs = (const float*)d_in[4];
    const float* Wks = (const float*)d_in[5];
    const float* Wvs = (const float*)d_in[6];
    const float* lq1 = (const float*)d_in[7];
    const float* lq2 = (const float*)d_in[8];
    const float* lk1 = (const float*)d_in[9];
    const float* lk2 = (const float*)d_in[10];
    const float* gam = (const float*)d_in[11];
    const float* bet = (const float*)d_in[12];
    float* out = (float*)d_out;

    size_t asmem = (size_t)(64*132 + 64*68 + 128*68 + 64*128) * sizeof(float);
    cudaFuncSetAttribute(attn_kernel, cudaFuncAttributeMaxDynamicSharedMemorySize, (int)asmem);
    size_t psmem = 2 * PRJ_STAGEB;   // 147456
    cudaFuncSetAttribute(proj_mma, cudaFuncAttributeMaxDynamicSharedMemorySize, (int)psmem);

    lam_kernel<<<1, 32>>>(lq1, lq2, lk1, lk2);
    split_x<<<T_, 256>>>(x);
    transp_w<<<dim3(64, 4, 48), 256>>>(Wq, Wk, Wv);
    proj_mma<<<dim3(16, 16, 3), 256, psmem>>>();
    proj_fix<<<dim3(16, 3), 128>>>(x, Wqs, Wks, Wvs);
    attn_kernel<<<512, 256, asmem>>>();
    final_kernel<<<32768, 128>>>(gam, bet, out);
}

// round 7
// speedup vs baseline: 2.6599x; 1.4909x over previous
#include <cuda_runtime.h>
#include <cuda_fp16.h>
#include <math.h>
#include <cstdint>

#define H_   16
#define T_   2048
#define DIM_ 2048
#define DK_  64
#define E2_  128
#define LAMBDA_INIT_ 0.6192834728526787f
#define OUT_SCALE_   0.3807165271473213f
#define EPS_ 1e-5f

// ---------------- scratch ----------------------------------------------------
__device__ float g_att1[H_*T_*E2_];
__device__ float g_att2[H_*T_*E2_];
__device__ float g_lam[H_];
__device__ __align__(256) __half g_xhi[T_*DIM_];
__device__ __align__(256) __half g_xlo[T_*DIM_];
__device__ __align__(256) __half g_wthi[3*H_*E2_*DIM_];   // [sel][h][e][d]
__device__ __align__(256) __half g_wtlo[3*H_*E2_*DIM_];
__device__ __align__(256) __half g_qh[H_*T_*E2_];
__device__ __align__(256) __half g_ql[H_*T_*E2_];
__device__ __align__(256) __half g_kh[H_*T_*E2_];
__device__ __align__(256) __half g_kl[H_*T_*E2_];
__device__ __align__(256) __half g_vh[H_*T_*E2_];
__device__ __align__(256) __half g_vl[H_*T_*E2_];

// ---------------- helpers ----------------------------------------------------
__device__ __forceinline__ uint32_t smem_to_u32(const void* p) {
    uint32_t a;
    asm("{ .reg .u64 t; cvta.to.shared.u64 t, %1; cvt.u32.u64 %0, t; }" : "=r"(a) : "l"(p));
    return a;
}
#define LDSM4(r, addr) \
    asm volatile("ldmatrix.sync.aligned.m8n8.x4.shared.b16 {%0,%1,%2,%3}, [%4];" \
        : "=r"((r)[0]), "=r"((r)[1]), "=r"((r)[2]), "=r"((r)[3]) : "r"(addr))
#define LDSMT4(r, addr) \
    asm volatile("ldmatrix.sync.aligned.m8n8.x4.trans.shared.b16 {%0,%1,%2,%3}, [%4];" \
        : "=r"((r)[0]), "=r"((r)[1]), "=r"((r)[2]), "=r"((r)[3]) : "r"(addr))
#define MMA16816(c, a, b) \
    asm volatile("mma.sync.aligned.m16n8k16.row.col.f32.f16.f16.f32 " \
        "{%0,%1,%2,%3}, {%4,%5,%6,%7}, {%8,%9}, {%0,%1,%2,%3};" \
        : "+f"((c)[0]), "+f"((c)[1]), "+f"((c)[2]), "+f"((c)[3]) \
        : "r"((a)[0]), "r"((a)[1]), "r"((a)[2]), "r"((a)[3]), "r"((b)[0]), "r"((b)[1]))
#define CP_ASYNC16(sa, ga) \
    asm volatile("cp.async.cg.shared.global [%0], [%1], 16;" :: "r"(sa), "l"(ga))
#define CP_COMMIT() asm volatile("cp.async.commit_group;" ::: "memory")

__device__ __forceinline__ uint32_t packh2(__half a, __half b) {
    __half2 h = __halves2half2(a, b);
    return *(uint32_t*)&h;
}

// ---------------- lambda -----------------------------------------------------
__global__ void lam_kernel(const float* __restrict__ lq1, const float* __restrict__ lq2,
                           const float* __restrict__ lk1, const float* __restrict__ lk2) {
    int h = threadIdx.x;
    if (h < H_) {
        float d1 = 0.f, d2 = 0.f;
        for (int d = 0; d < DK_; d++) {
            d1 += lq1[h*DK_ + d] * lk1[h*DK_ + d];
            d2 += lq2[h*DK_ + d] * lk2[h*DK_ + d];
        }
        g_lam[h] = expf(d1) - expf(d2) + LAMBDA_INIT_;
    }
}

// ---------------- prep: split X into fp16 hi/lo ------------------------------
__global__ void __launch_bounds__(256) split_x(const float* __restrict__ X) {
    int t = blockIdx.x;
    const float* xp = X + (size_t)t * DIM_;
    __half* hp = g_xhi + (size_t)t * DIM_;
    __half* lp = g_xlo + (size_t)t * DIM_;
    for (int j = threadIdx.x; j < DIM_; j += 256) {
        float v = xp[j];
        __half hi = __float2half_rn(v);
        hp[j] = hi;
        lp[j] = __float2half_rn(v - __half2float(hi));
    }
}

// ---------------- prep: transpose + split W ----------------------------------
__global__ void __launch_bounds__(256) transp_w(const float* __restrict__ Wq,
                                                const float* __restrict__ Wk,
                                                const float* __restrict__ Wv) {
    __shared__ float tile[32][33];
    int hs = blockIdx.z;
    int sel = hs >> 4, h = hs & 15;
    const float* W = sel == 0 ? Wq : (sel == 1 ? Wk : Wv);
    int d0 = blockIdx.x * 32;
    int e0 = blockIdx.y * 32;
    int tx = threadIdx.x & 31, ty = threadIdx.x >> 5;
    #pragma unroll
    for (int i = 0; i < 4; i++) {
        int d = d0 + ty + i * 8;
        tile[ty + i * 8][tx] = W[((size_t)h * DIM_ + d) * E2_ + e0 + tx];
    }
    __syncthreads();
    #pragma unroll
    for (int i = 0; i < 4; i++) {
        int e = e0 + ty + i * 8;
        float v = tile[tx][ty + i * 8];
        __half hi = __float2half_rn(v);
        size_t idx = ((size_t)hs * E2_ + e) * DIM_ + d0 + tx;
        g_wthi[idx] = hi;
        g_wtlo[idx] = __float2half_rn(v - __half2float(hi));
    }
}

// ---------------- projection via mma.sync split-fp16 -------------------------
#define PRJ_ROWB   144
#define PRJ_TILEB  (128*PRJ_ROWB)
#define PRJ_STAGEB (4*PRJ_TILEB)

__global__ void __launch_bounds__(256) proj_mma() {
    extern __shared__ char smc[];
    uint32_t sbase = smem_to_u32(smc);
    int tid = threadIdx.x, lane = tid & 31, wid = tid >> 5;
    int tblk = blockIdx.x, h = blockIdx.y, sel = blockIdx.z;
    int row0 = tblk * 128;

    const char* gA0 = (const char*)g_xhi + (size_t)row0 * (DIM_ * 2);
    const char* gA1 = (const char*)g_xlo + (size_t)row0 * (DIM_ * 2);
    size_t wofs = (size_t)(sel * H_ + h) * E2_ * (DIM_ * 2);
    const char* gA2 = (const char*)g_wthi + wofs;
    const char* gA3 = (const char*)g_wtlo + wofs;

    int m0 = (wid >> 1) * 32, n0 = (wid & 1) * 64;
    float acc[2][8][4] = {};

    auto issue = [&](int s, int b) {
        uint32_t sb = sbase + b * PRJ_STAGEB;
        size_t k0b = (size_t)s * 128;
        #pragma unroll
        for (int i = 0; i < 4; i++) {
            int l = tid + i * 256;
            int row = l >> 3, seg = l & 7;
            size_t gofs = (size_t)row * (DIM_ * 2) + k0b + seg * 16;
            uint32_t sofs = row * PRJ_ROWB + seg * 16;
            CP_ASYNC16(sb + 0 * PRJ_TILEB + sofs, gA0 + gofs);
            CP_ASYNC16(sb + 1 * PRJ_TILEB + sofs, gA1 + gofs);
            CP_ASYNC16(sb + 2 * PRJ_TILEB + sofs, gA2 + gofs);
            CP_ASYNC16(sb + 3 * PRJ_TILEB + sofs, gA3 + gofs);
        }
        CP_COMMIT();
    };

    issue(0, 0);
    for (int s = 0; s < 32; s++) {
        int b = s & 1;
        if (s < 31) issue(s + 1, b ^ 1);
        if (s < 31) asm volatile("cp.async.wait_group 1;" ::: "memory");
        else        asm volatile("cp.async.wait_group 0;" ::: "memory");
        __syncthreads();

        uint32_t sAh = sbase + b * PRJ_STAGEB;
        uint32_t sAl = sAh + PRJ_TILEB;
        uint32_t sBh = sAl + PRJ_TILEB;
        uint32_t sBl = sBh + PRJ_TILEB;
        #pragma unroll
        for (int kk = 0; kk < 64; kk += 16) {
            uint32_t ah[2][4], al[2][4];
            #pragma unroll
            for (int mt = 0; mt < 2; mt++) {
                uint32_t off = (uint32_t)(m0 + mt * 16 + (lane & 15)) * PRJ_ROWB
                             + (kk + (lane >> 4) * 8) * 2;
                LDSM4(ah[mt], sAh + off);
                LDSM4(al[mt], sAl + off);
            }
            uint32_t bh[4][4], bl[4][4];
            #pragma unroll
            for (int np = 0; np < 4; np++) {
                uint32_t off = (uint32_t)(n0 + np * 16 + (lane & 7) + ((lane >> 4) & 1) * 8) * PRJ_ROWB
                             + (kk + ((lane >> 3) & 1) * 8) * 2;
                LDSM4(bh[np], sBh + off);
                LDSM4(bl[np], sBl + off);
            }
            #pragma unroll
            for (int mt = 0; mt < 2; mt++)
                #pragma unroll
                for (int nt = 0; nt < 8; nt++) {
                    uint32_t* bhp = &bh[nt >> 1][(nt & 1) * 2];
                    uint32_t* blp = &bl[nt >> 1][(nt & 1) * 2];
                    MMA16816(acc[mt][nt], ah[mt], bhp);
                    MMA16816(acc[mt][nt], ah[mt], blp);
                    MMA16816(acc[mt][nt], al[mt], bhp);
                }
        }
        __syncthreads();
    }

    __half* Gh = (sel == 0 ? g_qh : (sel == 1 ? g_kh : g_vh)) + (size_t)h * T_ * E2_;
    __half* Gl = (sel == 0 ? g_ql : (sel == 1 ? g_kl : g_vl)) + (size_t)h * T_ * E2_;
    #pragma unroll
    for (int mt = 0; mt < 2; mt++)
        #pragma unroll
        for (int nt = 0; nt < 8; nt++) {
            int r = row0 + m0 + mt * 16 + (lane >> 2);
            int c = n0 + nt * 8 + (lane & 3) * 2;
            #pragma unroll
            for (int half2i = 0; half2i < 2; half2i++) {
                float v0 = acc[mt][nt][half2i * 2 + 0];
                float v1 = acc[mt][nt][half2i * 2 + 1];
                __half h0 = __float2half_rn(v0), h1 = __float2half_rn(v1);
                __half l0 = __float2half_rn(v0 - __half2float(h0));
                __half l1 = __float2half_rn(v1 - __half2float(h1));
                size_t o = (size_t)(r + half2i * 8) * E2_ + c;
                *(uint32_t*)&Gh[o] = packh2(h0, h1);
                *(uint32_t*)&Gl[o] = packh2(l0, l1);
            }
        }
}

// ---------------- fix-up: recompute 16 state rows with W_s (fp32) ------------
__global__ void __launch_bounds__(128) proj_fix(const float* __restrict__ X,
                                                const float* __restrict__ Wqs,
                                                const float* __restrict__ Wks,
                                                const float* __restrict__ Wvs) {
    __shared__ float xs[512][16];
    int h = blockIdx.x;
    int z = blockIdx.y;
    const float* Ws = z == 0 ? Wqs : (z == 1 ? Wks : Wvs);
    __half* Gh = (z == 0 ? g_qh : (z == 1 ? g_kh : g_vh));
    __half* Gl = (z == 0 ? g_ql : (z == 1 ? g_kl : g_vl));
    int e = threadIdx.x;
    const float* Wp = Ws + (size_t)h * DIM_ * E2_ + e;
    float acc[16] = {};
    for (int d0 = 0; d0 < DIM_; d0 += 512) {
        __syncthreads();
        for (int l = threadIdx.x; l < 16 * 512; l += 128) {
            int ti = l >> 9;
            int c  = l & 511;
            int t  = ti < 8 ? ti : 2032 + ti;
            xs[c][ti] = X[(size_t)t * DIM_ + d0 + c];
        }
        __syncthreads();
        for (int c = 0; c < 512; c++) {
            float w = Wp[(size_t)(d0 + c) * E2_];
            float4 x0 = *(const float4*)&xs[c][0];
            float4 x1 = *(const float4*)&xs[c][4];
            float4 x2 = *(const float4*)&xs[c][8];
            float4 x3 = *(const float4*)&xs[c][12];
            acc[0]  = fmaf(x0.x, w, acc[0]);   acc[1]  = fmaf(x0.y, w, acc[1]);
            acc[2]  = fmaf(x0.z, w, acc[2]);   acc[3]  = fmaf(x0.w, w, acc[3]);
            acc[4]  = fmaf(x1.x, w, acc[4]);   acc[5]  = fmaf(x1.y, w, acc[5]);
            acc[6]  = fmaf(x1.z, w, acc[6]);   acc[7]  = fmaf(x1.w, w, acc[7]);
            acc[8]  = fmaf(x2.x, w, acc[8]);   acc[9]  = fmaf(x2.y, w, acc[9]);
            acc[10] = fmaf(x2.z, w, acc[10]);  acc[11] = fmaf(x2.w, w, acc[11]);
            acc[12] = fmaf(x3.x, w, acc[12]);  acc[13] = fmaf(x3.y, w, acc[13]);
            acc[14] = fmaf(x3.z, w, acc[14]);  acc[15] = fmaf(x3.w, w, acc[15]);
        }
    }
    #pragma unroll
    for (int ti = 0; ti < 16; ti++) {
        int t = ti < 8 ? ti : 2032 + ti;
        size_t idx = (size_t)h * T_ * E2_ + (size_t)t * E2_ + e;
        float v = acc[ti];
        __half hi = __float2half_rn(v);
        Gh[idx] = hi;
        Gl[idx] = __float2half_rn(v - __half2float(hi));
    }
}

// ---------------- flash attention via mma.sync -------------------------------
// CTA: 128 q-rows x head x stream; 8 warps (16 rows each).
#define AT_ROWB  144
#define AT_VROWB 272
#define AT_QH    0
#define AT_QL    (128*AT_ROWB)             // 18432
#define AT_ST0   (2*128*AT_ROWB)           // 36864
#define AT_KH    0
#define AT_KL    (64*AT_ROWB)              // 9216
#define AT_VH    (2*64*AT_ROWB)            // 18432
#define AT_VL    (2*64*AT_ROWB + 64*AT_VROWB)  // 35840
#define AT_STAGE (2*64*AT_ROWB + 2*64*AT_VROWB) // 53248
#define AT_SMEM  (AT_ST0 + 2*AT_STAGE)     // 143360

__global__ void __launch_bounds__(256) attn_kernel() {
    extern __shared__ char smc[];
    uint32_t sbase = smem_to_u32(smc);
    int tid = threadIdx.x, lane = tid & 31, wid = tid >> 5;
    int bid = (int)blockIdx.x;
    int qb = 15 - (bid >> 5);
    int rem = bid & 31;
    int h = rem >> 1;
    int which = rem & 1;
    int t0 = qb * 128;

    size_t hbase = (size_t)h * T_ * E2_;
    const char* Qh = (const char*)(g_qh + hbase + (size_t)t0 * E2_ + which * DK_);
    const char* Ql = (const char*)(g_ql + hbase + (size_t)t0 * E2_ + which * DK_);
    const char* Kh = (const char*)(g_kh + hbase + which * DK_);
    const char* Kl = (const char*)(g_kl + hbase + which * DK_);
    const char* Vh = (const char*)(g_vh + hbase);
    const char* Vl = (const char*)(g_vl + hbase);
    float* Ao = (which ? g_att2 : g_att1) + hbase + (size_t)t0 * E2_;

    // issue Q (128 rows x 128B per array)
    #pragma unroll
    for (int i = 0; i < 4; i++) {
        int l = tid + i * 256;
        int row = l >> 3, seg = l & 7;
        uint32_t so = row * AT_ROWB + seg * 16;
        size_t go = (size_t)row * 256 + seg * 16;
        CP_ASYNC16(sbase + AT_QH + so, Qh + go);
        CP_ASYNC16(sbase + AT_QL + so, Ql + go);
    }
    CP_COMMIT();

    auto issue_kv = [&](int kb, int b) {
        uint32_t sb = sbase + AT_ST0 + b * AT_STAGE;
        size_t kofs = (size_t)kb * 64 * 256;
        #pragma unroll
        for (int i = 0; i < 2; i++) {
            int l = tid + i * 256;
            int row = l >> 3, seg = l & 7;
            uint32_t so = row * AT_ROWB + seg * 16;
            size_t go = kofs + (size_t)row * 256 + seg * 16;
            CP_ASYNC16(sb + AT_KH + so, Kh + go);
            CP_ASYNC16(sb + AT_KL + so, Kl + go);
        }
        #pragma unroll
        for (int i = 0; i < 4; i++) {
            int l = tid + i * 256;
            int row = l >> 4, seg = l & 15;
            uint32_t so = row * AT_VROWB + seg * 16;
            size_t go = kofs + (size_t)row * 256 + seg * 16;
            CP_ASYNC16(sb + AT_VH + so, Vh + go);
            CP_ASYNC16(sb + AT_VL + so, Vl + go);
        }
        CP_COMMIT();
    };

    issue_kv(0, 0);
    asm volatile("cp.async.wait_group 1;" ::: "memory");
    __syncthreads();

    // Q fragments (persist all iterations)
    uint32_t qh[4][4], ql[4][4];
    #pragma unroll
    for (int kt = 0; kt < 4; kt++) {
        uint32_t off = (uint32_t)(wid * 16 + (lane & 15)) * AT_ROWB
                     + (kt * 16 + (lane >> 4) * 8) * 2;
        LDSM4(qh[kt], sbase + AT_QH + off);
        LDSM4(ql[kt], sbase + AT_QL + off);
    }

    float o[16][4] = {};
    float mA = -INFINITY, mB = -INFINITY, lA = 0.f, lB = 0.f;
    int nkb = 2 * qb + 2;

    for (int kb = 0; kb < nkb; kb++) {
        int b = kb & 1;
        if (kb + 1 < nkb) {
            issue_kv(kb + 1, b ^ 1);
            asm volatile("cp.async.wait_group 1;" ::: "memory");
        } else {
            asm volatile("cp.async.wait_group 0;" ::: "memory");
        }
        __syncthreads();

        uint32_t sb = sbase + AT_ST0 + b * AT_STAGE;

        // ---- S = Q K^T (m16 x n64 per warp), split hi/lo ----
        float s[8][4] = {};
        #pragma unroll
        for (int kt = 0; kt < 4; kt++) {
            uint32_t kfh[4][4], kfl[4][4];
            #pragma unroll
            for (int np = 0; np < 4; np++) {
                uint32_t off = (uint32_t)(np * 16 + (lane & 7) + ((lane >> 4) & 1) * 8) * AT_ROWB
                             + (kt * 16 + ((lane >> 3) & 1) * 8) * 2;
                LDSM4(kfh[np], sb + AT_KH + off);
                LDSM4(kfl[np], sb + AT_KL + off);
            }
            #pragma unroll
            for (int nt = 0; nt < 8; nt++) {
                uint32_t* bh = &kfh[nt >> 1][(nt & 1) * 2];
                uint32_t* bl = &kfl[nt >> 1][(nt & 1) * 2];
                MMA16816(s[nt], qh[kt], bh);
                MMA16816(s[nt], ql[kt], bh);
                MMA16816(s[nt], qh[kt], bl);
            }
        }

        // ---- scale + causal mask ----
        bool diag = (kb >= 2 * qb);
        int rA = t0 + wid * 16 + (lane >> 2);
        #pragma unroll
        for (int nt = 0; nt < 8; nt++)
            #pragma unroll
            for (int e = 0; e < 4; e++) {
                float v = s[nt][e] * 0.125f;
                if (diag) {
                    int jc = kb * 64 + nt * 8 + (lane & 3) * 2 + (e & 1);
                    int ir = rA + (e >> 1) * 8;
                    if (jc > ir) v = -1e30f;
                }
                s[nt][e] = v;
            }

        // ---- online softmax (rows A = lane>>2, B = A+8 within warp) ----
        float rmA = -INFINITY, rmB = -INFINITY;
        #pragma unroll
        for (int nt = 0; nt < 8; nt++) {
            rmA = fmaxf(rmA, fmaxf(s[nt][0], s[nt][1]));
            rmB = fmaxf(rmB, fmaxf(s[nt][2], s[nt][3]));
        }
        rmA = fmaxf(rmA, __shfl_xor_sync(0xffffffffu, rmA, 1));
        rmA = fmaxf(rmA, __shfl_xor_sync(0xffffffffu, rmA, 2));
        rmB = fmaxf(rmB, __shfl_xor_sync(0xffffffffu, rmB, 1));
        rmB = fmaxf(rmB, __shfl_xor_sync(0xffffffffu, rmB, 2));
        float nmA = fmaxf(mA, rmA), nmB = fmaxf(mB, rmB);
        float aA = __expf(mA - nmA), aB = __expf(mB - nmB);
        mA = nmA; mB = nmB;
        float rsA = 0.f, rsB = 0.f;
        #pragma unroll
        for (int nt = 0; nt < 8; nt++) {
            s[nt][0] = __expf(s[nt][0] - nmA);
            s[nt][1] = __expf(s[nt][1] - nmA);
            s[nt][2] = __expf(s[nt][2] - nmB);
            s[nt][3] = __expf(s[nt][3] - nmB);
            rsA += s[nt][0] + s[nt][1];
            rsB += s[nt][2] + s[nt][3];
        }
        rsA += __shfl_xor_sync(0xffffffffu, rsA, 1);
        rsA += __shfl_xor_sync(0xffffffffu, rsA, 2);
        rsB += __shfl_xor_sync(0xffffffffu, rsB, 1);
        rsB += __shfl_xor_sync(0xffffffffu, rsB, 2);
        lA = lA * aA + rsA;
        lB = lB * aB + rsB;
        #pragma unroll
        for (int nt = 0; nt < 16; nt++) {
            o[nt][0] *= aA; o[nt][1] *= aA;
            o[nt][2] *= aB; o[nt][3] *= aB;
        }

        // ---- pack P as A fragments (hi/lo) ----
        uint32_t ph[4][4], pl[4][4];
        #pragma unroll
        for (int kt = 0; kt < 4; kt++)
            #pragma unroll
            for (int half16 = 0; half16 < 2; half16++) {
                float* e = s[2 * kt + half16];
                __half h0 = __float2half_rn(e[0]), h1 = __float2half_rn(e[1]);
                __half h2 = __float2half_rn(e[2]), h3 = __float2half_rn(e[3]);
                ph[kt][half16 * 2 + 0] = packh2(h0, h1);
                ph[kt][half16 * 2 + 1] = packh2(h2, h3);
                pl[kt][half16 * 2 + 0] = packh2(__float2half_rn(e[0] - __half2float(h0)),
                                                __float2half_rn(e[1] - __half2float(h1)));
                pl[kt][half16 * 2 + 1] = packh2(__float2half_rn(e[2] - __half2float(h2)),
                                                __float2half_rn(e[3] - __half2float(h3)));
            }

        // ---- O += P V (m16 x n128 per warp), split ----
        #pragma unroll
        for (int kt = 0; kt < 4; kt++) {
            #pragma unroll
            for (int vn = 0; vn < 8; vn++) {
                uint32_t off = (uint32_t)(kt * 16 + (lane & 15)) * AT_VROWB
                             + (vn * 16 + (lane >> 4) * 8) * 2;
                uint32_t vf[4], vg[4];
                LDSMT4(vf, sb + AT_VH + off);
                LDSMT4(vg, sb + AT_VL + off);
                MMA16816(o[2 * vn + 0], ph[kt], &vf[0]);
                MMA16816(o[2 * vn + 0], pl[kt], &vf[0]);
                MMA16816(o[2 * vn + 0], ph[kt], &vg[0]);
                MMA16816(o[2 * vn + 1], ph[kt], &vf[2]);
                MMA16816(o[2 * vn + 1], pl[kt], &vf[2]);
                MMA16816(o[2 * vn + 1], ph[kt], &vg[2]);
            }
        }
        __syncthreads();   // all reads of buffer b done before next issue overwrites
    }

    float invA = 1.f / lA, invB = 1.f / lB;
    int rloc = wid * 16 + (lane >> 2);
    #pragma unroll
    for (int nt = 0; nt < 16; nt++) {
        int c = nt * 8 + (lane & 3) * 2;
        *(float2*)&Ao[(size_t)rloc * E2_ + c] = make_float2(o[nt][0] * invA, o[nt][1] * invA);
        *(float2*)&Ao[(size_t)(rloc + 8) * E2_ + c] = make_float2(o[nt][2] * invB, o[nt][3] * invB);
    }
}

// ---------------- combine + layernorm + scale --------------------------------
__global__ void __launch_bounds__(128) final_kernel(const float* __restrict__ gamma,
                                                    const float* __restrict__ beta,
                                                    float* __restrict__ Out) {
    int h = blockIdx.x >> 11;
    int t = blockIdx.x & 2047;
    int e = threadIdx.x;
    size_t base = ((size_t)h * T_ + t) * E2_;
    float a1 = g_att1[base + e];
    float a2 = g_att2[base + e];
    float v = a1 - g_lam[h] * a2;

    float s1 = v, s2 = v * v;
    #pragma unroll
    for (int off = 16; off; off >>= 1) {
        s1 += __shfl_xor_sync(0xffffffffu, s1, off);
        s2 += __shfl_xor_sync(0xffffffffu, s2, off);
    }
    __shared__ float red[8];
    int w = e >> 5, lane = e & 31;
    if (lane == 0) { red[w] = s1; red[4 + w] = s2; }
    __syncthreads();
    float sum = red[0] + red[1] + red[2] + red[3];
    float sq  = red[4] + red[5] + red[6] + red[7];
    float mu  = sum * (1.f / 128.f);
    float var = fmaxf(sq * (1.f / 128.f) - mu * mu, 0.f);
    float nv  = (v - mu) * rsqrtf(var + EPS_);
    Out[base + e] = (nv * gamma[h * E2_ + e] + beta[h * E2_ + e]) * OUT_SCALE_;
}

// ---------------- launch -----------------------------------------------------
extern "C" void kernel_launch(void* const* d_in, const int* in_sizes, int n_in,
                              void* d_out, int out_size) {
    const float* x   = (const float*)d_in[0];
    const float* Wq  = (const float*)d_in[1];
    const float* Wk  = (const float*)d_in[2];
    const float* Wv  = (const float*)d_in[3];
    const float* Wqs = (const float*)d_in[4];
    const float* Wks = (const float*)d_in[5];
    const float* Wvs = (const float*)d_in[6];
    const float* lq1 = (const float*)d_in[7];
    const float* lq2 = (const float*)d_in[8];
    const float* lk1 = (const float*)d_in[9];
    const float* lk2 = (const float*)d_in[10];
    const float* gam = (const float*)d_in[11];
    const float* bet = (const float*)d_in[12];
    float* out = (float*)d_out;

    size_t psmem = 2 * PRJ_STAGEB;   // 147456
    cudaFuncSetAttribute(proj_mma, cudaFuncAttributeMaxDynamicSharedMemorySize, (int)psmem);
    cudaFuncSetAttribute(attn_kernel, cudaFuncAttributeMaxDynamicSharedMemorySize, AT_SMEM);

    lam_kernel<<<1, 32>>>(lq1, lq2, lk1, lk2);
    split_x<<<T_, 256>>>(x);
    transp_w<<<dim3(64, 4, 48), 256>>>(Wq, Wk, Wv);
    proj_mma<<<dim3(16, 16, 3), 256, psmem>>>();
    proj_fix<<<dim3(16, 3), 128>>>(x, Wqs, Wks, Wvs);
    attn_kernel<<<512, 256, AT_SMEM>>>();
    final_kernel<<<32768, 128>>>(gam, bet, out);
}

// round 8
// speedup vs baseline: 3.1946x; 1.2010x over previous
#include <cuda_runtime.h>
#include <cuda_fp16.h>
#include <math.h>
#include <cstdint>

#define H_   16
#define T_   2048
#define DIM_ 2048
#define DK_  64
#define E2_  128
#define LAMBDA_INIT_ 0.6192834728526787f
#define OUT_SCALE_   0.3807165271473213f
#define EPS_ 1e-5f

// ---------------- scratch ----------------------------------------------------
__device__ float g_att1[H_*T_*E2_];
__device__ float g_att2[H_*T_*E2_];
__device__ float g_lam[H_];
__device__ __align__(256) __half g_xhi[T_*DIM_];
__device__ __align__(256) __half g_xlo[T_*DIM_];
__device__ __align__(256) __half g_wthi[3*H_*E2_*DIM_];   // [sel][h][e][d]
__device__ __align__(256) __half g_wtlo[3*H_*E2_*DIM_];
__device__ __align__(256) __half g_qh[H_*T_*E2_];
__device__ __align__(256) __half g_ql[H_*T_*E2_];
__device__ __align__(256) __half g_kh[H_*T_*E2_];
__device__ __align__(256) __half g_kl[H_*T_*E2_];
__device__ __align__(256) __half g_vh[H_*T_*E2_];
__device__ __align__(256) __half g_vl[H_*T_*E2_];

// ---------------- helpers ----------------------------------------------------
__device__ __forceinline__ uint32_t smem_to_u32(const void* p) {
    uint32_t a;
    asm("{ .reg .u64 t; cvta.to.shared.u64 t, %1; cvt.u32.u64 %0, t; }" : "=r"(a) : "l"(p));
    return a;
}
#define LDSM4(r, addr) \
    asm volatile("ldmatrix.sync.aligned.m8n8.x4.shared.b16 {%0,%1,%2,%3}, [%4];" \
        : "=r"((r)[0]), "=r"((r)[1]), "=r"((r)[2]), "=r"((r)[3]) : "r"(addr))
#define LDSMT4(r, addr) \
    asm volatile("ldmatrix.sync.aligned.m8n8.x4.trans.shared.b16 {%0,%1,%2,%3}, [%4];" \
        : "=r"((r)[0]), "=r"((r)[1]), "=r"((r)[2]), "=r"((r)[3]) : "r"(addr))
#define MMA16816(c, a, b) \
    asm volatile("mma.sync.aligned.m16n8k16.row.col.f32.f16.f16.f32 " \
        "{%0,%1,%2,%3}, {%4,%5,%6,%7}, {%8,%9}, {%0,%1,%2,%3};" \
        : "+f"((c)[0]), "+f"((c)[1]), "+f"((c)[2]), "+f"((c)[3]) \
        : "r"((a)[0]), "r"((a)[1]), "r"((a)[2]), "r"((a)[3]), "r"((b)[0]), "r"((b)[1]))
#define CP_ASYNC16(sa, ga) \
    asm volatile("cp.async.cg.shared.global [%0], [%1], 16;" :: "r"(sa), "l"(ga))
#define CP_COMMIT() asm volatile("cp.async.commit_group;" ::: "memory")

__device__ __forceinline__ uint32_t packh2(__half a, __half b) {
    __half2 h = __halves2half2(a, b);
    return *(uint32_t*)&h;
}

// ---------------- lambda -----------------------------------------------------
__global__ void lam_kernel(const float* __restrict__ lq1, const float* __restrict__ lq2,
                           const float* __restrict__ lk1, const float* __restrict__ lk2) {
    int h = threadIdx.x;
    if (h < H_) {
        float d1 = 0.f, d2 = 0.f;
        for (int d = 0; d < DK_; d++) {
            d1 += lq1[h*DK_ + d] * lk1[h*DK_ + d];
            d2 += lq2[h*DK_ + d] * lk2[h*DK_ + d];
        }
        g_lam[h] = expf(d1) - expf(d2) + LAMBDA_INIT_;
    }
}

// ---------------- prep: split X into fp16 hi/lo ------------------------------
__global__ void __launch_bounds__(256) split_x(const float* __restrict__ X) {
    int t = blockIdx.x;
    const float* xp = X + (size_t)t * DIM_;
    __half* hp = g_xhi + (size_t)t * DIM_;
    __half* lp = g_xlo + (size_t)t * DIM_;
    for (int j = threadIdx.x; j < DIM_; j += 256) {
        float v = xp[j];
        __half hi = __float2half_rn(v);
        hp[j] = hi;
        lp[j] = __float2half_rn(v - __half2float(hi));
    }
}

// ---------------- prep: transpose + split W ----------------------------------
__global__ void __launch_bounds__(256) transp_w(const float* __restrict__ Wq,
                                                const float* __restrict__ Wk,
                                                const float* __restrict__ Wv) {
    __shared__ float tile[32][33];
    int hs = blockIdx.z;
    int sel = hs >> 4, h = hs & 15;
    const float* W = sel == 0 ? Wq : (sel == 1 ? Wk : Wv);
    int d0 = blockIdx.x * 32;
    int e0 = blockIdx.y * 32;
    int tx = threadIdx.x & 31, ty = threadIdx.x >> 5;
    #pragma unroll
    for (int i = 0; i < 4; i++) {
        int d = d0 + ty + i * 8;
        tile[ty + i * 8][tx] = W[((size_t)h * DIM_ + d) * E2_ + e0 + tx];
    }
    __syncthreads();
    #pragma unroll
    for (int i = 0; i < 4; i++) {
        int e = e0 + ty + i * 8;
        float v = tile[tx][ty + i * 8];
        __half hi = __float2half_rn(v);
        size_t idx = ((size_t)hs * E2_ + e) * DIM_ + d0 + tx;
        g_wthi[idx] = hi;
        g_wtlo[idx] = __float2half_rn(v - __half2float(hi));
    }
}

// ---------------- projection via mma.sync split-fp16 -------------------------
// K-chunk = 32 (2-stage, 41KB/stage) -> 2 CTAs/SM.
#define PRJ_ROWB   80
#define PRJ_TILEB  (128*PRJ_ROWB)        // 10240
#define PRJ_STAGEB (4*PRJ_TILEB)         // 40960
#define PRJ_NSTG   64                    // 2048 / 32

__global__ void __launch_bounds__(256, 2) proj_mma() {
    extern __shared__ char smc[];
    uint32_t sbase = smem_to_u32(smc);
    int tid = threadIdx.x, lane = tid & 31, wid = tid >> 5;
    int tblk = blockIdx.x, h = blockIdx.y, sel = blockIdx.z;
    int row0 = tblk * 128;

    const char* gA0 = (const char*)g_xhi + (size_t)row0 * (DIM_ * 2);
    const char* gA1 = (const char*)g_xlo + (size_t)row0 * (DIM_ * 2);
    size_t wofs = (size_t)(sel * H_ + h) * E2_ * (DIM_ * 2);
    const char* gA2 = (const char*)g_wthi + wofs;
    const char* gA3 = (const char*)g_wtlo + wofs;

    int m0 = (wid >> 1) * 32, n0 = (wid & 1) * 64;
    float acc[2][8][4] = {};

    // issue one K-stage (32 k = 64B per row) into buffer b
    auto issue = [&](int s, int b) {
        uint32_t sb = sbase + b * PRJ_STAGEB;
        size_t k0b = (size_t)s * 64;
        #pragma unroll
        for (int i = 0; i < 2; i++) {
            int l = tid + i * 256;
            int row = l >> 2, seg = l & 3;
            size_t gofs = (size_t)row * (DIM_ * 2) + k0b + seg * 16;
            uint32_t sofs = row * PRJ_ROWB + seg * 16;
            CP_ASYNC16(sb + 0 * PRJ_TILEB + sofs, gA0 + gofs);
            CP_ASYNC16(sb + 1 * PRJ_TILEB + sofs, gA1 + gofs);
            CP_ASYNC16(sb + 2 * PRJ_TILEB + sofs, gA2 + gofs);
            CP_ASYNC16(sb + 3 * PRJ_TILEB + sofs, gA3 + gofs);
        }
        CP_COMMIT();
    };

    issue(0, 0);
    for (int s = 0; s < PRJ_NSTG; s++) {
        int b = s & 1;
        if (s < PRJ_NSTG - 1) issue(s + 1, b ^ 1);
        if (s < PRJ_NSTG - 1) asm volatile("cp.async.wait_group 1;" ::: "memory");
        else                  asm volatile("cp.async.wait_group 0;" ::: "memory");
        __syncthreads();

        uint32_t sAh = sbase + b * PRJ_STAGEB;
        uint32_t sAl = sAh + PRJ_TILEB;
        uint32_t sBh = sAl + PRJ_TILEB;
        uint32_t sBl = sBh + PRJ_TILEB;
        #pragma unroll
        for (int kk = 0; kk < 32; kk += 16) {
            uint32_t ah[2][4], al[2][4];
            #pragma unroll
            for (int mt = 0; mt < 2; mt++) {
                uint32_t off = (uint32_t)(m0 + mt * 16 + (lane & 15)) * PRJ_ROWB
                             + (kk + (lane >> 4) * 8) * 2;
                LDSM4(ah[mt], sAh + off);
                LDSM4(al[mt], sAl + off);
            }
            uint32_t bh[4][4], bl[4][4];
            #pragma unroll
            for (int np = 0; np < 4; np++) {
                uint32_t off = (uint32_t)(n0 + np * 16 + (lane & 7) + ((lane >> 4) & 1) * 8) * PRJ_ROWB
                             + (kk + ((lane >> 3) & 1) * 8) * 2;
                LDSM4(bh[np], sBh + off);
                LDSM4(bl[np], sBl + off);
            }
            #pragma unroll
            for (int mt = 0; mt < 2; mt++)
                #pragma unroll
                for (int nt = 0; nt < 8; nt++) {
                    uint32_t* bhp = &bh[nt >> 1][(nt & 1) * 2];
                    uint32_t* blp = &bl[nt >> 1][(nt & 1) * 2];
                    MMA16816(acc[mt][nt], ah[mt], bhp);
                    MMA16816(acc[mt][nt], ah[mt], blp);
                    MMA16816(acc[mt][nt], al[mt], bhp);
                }
        }
        __syncthreads();
    }

    __half* Gh = (sel == 0 ? g_qh : (sel == 1 ? g_kh : g_vh)) + (size_t)h * T_ * E2_;
    __half* Gl = (sel == 0 ? g_ql : (sel == 1 ? g_kl : g_vl)) + (size_t)h * T_ * E2_;
    #pragma unroll
    for (int mt = 0; mt < 2; mt++)
        #pragma unroll
        for (int nt = 0; nt < 8; nt++) {
            int r = row0 + m0 + mt * 16 + (lane >> 2);
            int c = n0 + nt * 8 + (lane & 3) * 2;
            #pragma unroll
            for (int half2i = 0; half2i < 2; half2i++) {
                float v0 = acc[mt][nt][half2i * 2 + 0];
                float v1 = acc[mt][nt][half2i * 2 + 1];
                __half h0 = __float2half_rn(v0), h1 = __float2half_rn(v1);
                __half l0 = __float2half_rn(v0 - __half2float(h0));
                __half l1 = __float2half_rn(v1 - __half2float(h1));
                size_t o = (size_t)(r + half2i * 8) * E2_ + c;
                *(uint32_t*)&Gh[o] = packh2(h0, h1);
                *(uint32_t*)&Gl[o] = packh2(l0, l1);
            }
        }
}

// ---------------- fix-up: recompute 16 state rows with W_s (fp32) ------------
// grid (16 h, 3 sel, 4 token-groups), 4 tokens per block.
__global__ void __launch_bounds__(128) proj_fix(const float* __restrict__ X,
                                                const float* __restrict__ Wqs,
                                                const float* __restrict__ Wks,
                                                const float* __restrict__ Wvs) {
    __shared__ float xs[512][4];
    int h = blockIdx.x;
    int z = blockIdx.y;
    int g = blockIdx.z;          // token group: tokens g*4 .. g*4+3
    const float* Ws = z == 0 ? Wqs : (z == 1 ? Wks : Wvs);
    __half* Gh = (z == 0 ? g_qh : (z == 1 ? g_kh : g_vh));
    __half* Gl = (z == 0 ? g_ql : (z == 1 ? g_kl : g_vl));
    int e = threadIdx.x;
    const float* Wp = Ws + (size_t)h * DIM_ * E2_ + e;
    float acc[4] = {};
    for (int d0 = 0; d0 < DIM_; d0 += 512) {
        __syncthreads();
        for (int l = threadIdx.x; l < 4 * 512; l += 128) {
            int ti = l >> 9;
            int c  = l & 511;
            int tok = g * 4 + ti;
            int t  = tok < 8 ? tok : 2032 + tok;
            xs[c][ti] = X[(size_t)t * DIM_ + d0 + c];
        }
        __syncthreads();
        for (int c = 0; c < 512; c++) {
            float w = Wp[(size_t)(d0 + c) * E2_];
            float4 x0 = *(const float4*)&xs[c][0];
            acc[0] = fmaf(x0.x, w, acc[0]);
            acc[1] = fmaf(x0.y, w, acc[1]);
            acc[2] = fmaf(x0.z, w, acc[2]);
            acc[3] = fmaf(x0.w, w, acc[3]);
        }
    }
    #pragma unroll
    for (int ti = 0; ti < 4; ti++) {
        int tok = g * 4 + ti;
        int t = tok < 8 ? tok : 2032 + tok;
        size_t idx = (size_t)h * T_ * E2_ + (size_t)t * E2_ + e;
        float v = acc[ti];
        __half hi = __float2half_rn(v);
        Gh[idx] = hi;
        Gl[idx] = __float2half_rn(v - __half2float(hi));
    }
}

// ---------------- flash attention via mma.sync -------------------------------
// CTA: 128 q-rows x head x stream; 8 warps (16 rows each).
#define AT_ROWB  144
#define AT_VROWB 272
#define AT_QH    0
#define AT_QL    (128*AT_ROWB)             // 18432
#define AT_ST0   (2*128*AT_ROWB)           // 36864
#define AT_KH    0
#define AT_KL    (64*AT_ROWB)              // 9216
#define AT_VH    (2*64*AT_ROWB)            // 18432
#define AT_VL    (2*64*AT_ROWB + 64*AT_VROWB)  // 35840
#define AT_STAGE (2*64*AT_ROWB + 2*64*AT_VROWB) // 53248
#define AT_SMEM  (AT_ST0 + 2*AT_STAGE)     // 143360

__global__ void __launch_bounds__(256) attn_kernel() {
    extern __shared__ char smc[];
    uint32_t sbase = smem_to_u32(smc);
    int tid = threadIdx.x, lane = tid & 31, wid = tid >> 5;
    int bid = (int)blockIdx.x;
    int qb = 15 - (bid >> 5);
    int rem = bid & 31;
    int h = rem >> 1;
    int which = rem & 1;
    int t0 = qb * 128;

    size_t hbase = (size_t)h * T_ * E2_;
    const char* Qh = (const char*)(g_qh + hbase + (size_t)t0 * E2_ + which * DK_);
    const char* Ql = (const char*)(g_ql + hbase + (size_t)t0 * E2_ + which * DK_);
    const char* Kh = (const char*)(g_kh + hbase + which * DK_);
    const char* Kl = (const char*)(g_kl + hbase + which * DK_);
    const char* Vh = (const char*)(g_vh + hbase);
    const char* Vl = (const char*)(g_vl + hbase);
    float* Ao = (which ? g_att2 : g_att1) + hbase + (size_t)t0 * E2_;

    // issue Q (128 rows x 128B per array)
    #pragma unroll
    for (int i = 0; i < 4; i++) {
        int l = tid + i * 256;
        int row = l >> 3, seg = l & 7;
        uint32_t so = row * AT_ROWB + seg * 16;
        size_t go = (size_t)row * 256 + seg * 16;
        CP_ASYNC16(sbase + AT_QH + so, Qh + go);
        CP_ASYNC16(sbase + AT_QL + so, Ql + go);
    }
    CP_COMMIT();

    auto issue_kv = [&](int kb, int b) {
        uint32_t sb = sbase + AT_ST0 + b * AT_STAGE;
        size_t kofs = (size_t)kb * 64 * 256;
        #pragma unroll
        for (int i = 0; i < 2; i++) {
            int l = tid + i * 256;
            int row = l >> 3, seg = l & 7;
            uint32_t so = row * AT_ROWB + seg * 16;
            size_t go = kofs + (size_t)row * 256 + seg * 16;
            CP_ASYNC16(sb + AT_KH + so, Kh + go);
            CP_ASYNC16(sb + AT_KL + so, Kl + go);
        }
        #pragma unroll
        for (int i = 0; i < 4; i++) {
            int l = tid + i * 256;
            int row = l >> 4, seg = l & 15;
            uint32_t so = row * AT_VROWB + seg * 16;
            size_t go = kofs + (size_t)row * 256 + seg * 16;
            CP_ASYNC16(sb + AT_VH + so, Vh + go);
            CP_ASYNC16(sb + AT_VL + so, Vl + go);
        }
        CP_COMMIT();
    };

    issue_kv(0, 0);
    asm volatile("cp.async.wait_group 1;" ::: "memory");
    __syncthreads();

    // Q fragments (persist all iterations)
    uint32_t qh[4][4], ql[4][4];
    #pragma unroll
    for (int kt = 0; kt < 4; kt++) {
        uint32_t off = (uint32_t)(wid * 16 + (lane & 15)) * AT_ROWB
                     + (kt * 16 + (lane >> 4) * 8) * 2;
        LDSM4(qh[kt], sbase + AT_QH + off);
        LDSM4(ql[kt], sbase + AT_QL + off);
    }

    float o[16][4] = {};
    float mA = -INFINITY, mB = -INFINITY, lA = 0.f, lB = 0.f;
    int nkb = 2 * qb + 2;

    for (int kb = 0; kb < nkb; kb++) {
        int b = kb & 1;
        if (kb + 1 < nkb) {
            issue_kv(kb + 1, b ^ 1);
            asm volatile("cp.async.wait_group 1;" ::: "memory");
        } else {
            asm volatile("cp.async.wait_group 0;" ::: "memory");
        }
        __syncthreads();

        uint32_t sb = sbase + AT_ST0 + b * AT_STAGE;

        // ---- S = Q K^T (m16 x n64 per warp), split hi/lo ----
        float s[8][4] = {};
        #pragma unroll
        for (int kt = 0; kt < 4; kt++) {
            uint32_t kfh[4][4], kfl[4][4];
            #pragma unroll
            for (int np = 0; np < 4; np++) {
                uint32_t off = (uint32_t)(np * 16 + (lane & 7) + ((lane >> 4) & 1) * 8) * AT_ROWB
                             + (kt * 16 + ((lane >> 3) & 1) * 8) * 2;
                LDSM4(kfh[np], sb + AT_KH + off);
                LDSM4(kfl[np], sb + AT_KL + off);
            }
            #pragma unroll
            for (int nt = 0; nt < 8; nt++) {
                uint32_t* bh = &kfh[nt >> 1][(nt & 1) * 2];
                uint32_t* bl = &kfl[nt >> 1][(nt & 1) * 2];
                MMA16816(s[nt], qh[kt], bh);
                MMA16816(s[nt], ql[kt], bh);
                MMA16816(s[nt], qh[kt], bl);
            }
        }

        // ---- scale + causal mask ----
        bool diag = (kb >= 2 * qb);
        int rA = t0 + wid * 16 + (lane >> 2);
        #pragma unroll
        for (int nt = 0; nt < 8; nt++)
            #pragma unroll
            for (int e = 0; e < 4; e++) {
                float v = s[nt][e] * 0.125f;
                if (diag) {
                    int jc = kb * 64 + nt * 8 + (lane & 3) * 2 + (e & 1);
                    int ir = rA + (e >> 1) * 8;
                    if (jc > ir) v = -1e30f;
                }
                s[nt][e] = v;
            }

        // ---- online softmax (rows A = lane>>2, B = A+8 within warp) ----
        float rmA = -INFINITY, rmB = -INFINITY;
        #pragma unroll
        for (int nt = 0; nt < 8; nt++) {
            rmA = fmaxf(rmA, fmaxf(s[nt][0], s[nt][1]));
            rmB = fmaxf(rmB, fmaxf(s[nt][2], s[nt][3]));
        }
        rmA = fmaxf(rmA, __shfl_xor_sync(0xffffffffu, rmA, 1));
        rmA = fmaxf(rmA, __shfl_xor_sync(0xffffffffu, rmA, 2));
        rmB = fmaxf(rmB, __shfl_xor_sync(0xffffffffu, rmB, 1));
        rmB = fmaxf(rmB, __shfl_xor_sync(0xffffffffu, rmB, 2));
        float nmA = fmaxf(mA, rmA), nmB = fmaxf(mB, rmB);
        float aA = __expf(mA - nmA), aB = __expf(mB - nmB);
        mA = nmA; mB = nmB;
        float rsA = 0.f, rsB = 0.f;
        #pragma unroll
        for (int nt = 0; nt < 8; nt++) {
            s[nt][0] = __expf(s[nt][0] - nmA);
            s[nt][1] = __expf(s[nt][1] - nmA);
            s[nt][2] = __expf(s[nt][2] - nmB);
            s[nt][3] = __expf(s[nt][3] - nmB);
            rsA += s[nt][0] + s[nt][1];
            rsB += s[nt][2] + s[nt][3];
        }
        rsA += __shfl_xor_sync(0xffffffffu, rsA, 1);
        rsA += __shfl_xor_sync(0xffffffffu, rsA, 2);
        rsB += __shfl_xor_sync(0xffffffffu, rsB, 1);
        rsB += __shfl_xor_sync(0xffffffffu, rsB, 2);
        lA = lA * aA + rsA;
        lB = lB * aB + rsB;
        #pragma unroll
        for (int nt = 0; nt < 16; nt++) {
            o[nt][0] *= aA; o[nt][1] *= aA;
            o[nt][2] *= aB; o[nt][3] *= aB;
        }

        // ---- pack P as A fragments (hi/lo) ----
        uint32_t ph[4][4], pl[4][4];
        #pragma unroll
        for (int kt = 0; kt < 4; kt++)
            #pragma unroll
            for (int half16 = 0; half16 < 2; half16++) {
                float* e = s[2 * kt + half16];
                __half h0 = __float2half_rn(e[0]), h1 = __float2half_rn(e[1]);
                __half h2 = __float2half_rn(e[2]), h3 = __float2half_rn(e[3]);
                ph[kt][half16 * 2 + 0] = packh2(h0, h1);
                ph[kt][half16 * 2 + 1] = packh2(h2, h3);
                pl[kt][half16 * 2 + 0] = packh2(__float2half_rn(e[0] - __half2float(h0)),
                                                __float2half_rn(e[1] - __half2float(h1)));
                pl[kt][half16 * 2 + 1] = packh2(__float2half_rn(e[2] - __half2float(h2)),
                                                __float2half_rn(e[3] - __half2float(h3)));
            }

        // ---- O += P V (m16 x n128 per warp), split ----
        #pragma unroll
        for (int kt = 0; kt < 4; kt++) {
            #pragma unroll
            for (int vn = 0; vn < 8; vn++) {
                uint32_t off = (uint32_t)(kt * 16 + (lane & 15)) * AT_VROWB
                             + (vn * 16 + (lane >> 4) * 8) * 2;
                uint32_t vf[4], vg[4];
                LDSMT4(vf, sb + AT_VH + off);
                LDSMT4(vg, sb + AT_VL + off);
                MMA16816(o[2 * vn + 0], ph[kt], &vf[0]);
                MMA16816(o[2 * vn + 0], pl[kt], &vf[0]);
                MMA16816(o[2 * vn + 0], ph[kt], &vg[0]);
                MMA16816(o[2 * vn + 1], ph[kt], &vf[2]);
                MMA16816(o[2 * vn + 1], pl[kt], &vf[2]);
                MMA16816(o[2 * vn + 1], ph[kt], &vg[2]);
            }
        }
        __syncthreads();   // all reads of buffer b done before next issue overwrites
    }

    float invA = 1.f / lA, invB = 1.f / lB;
    int rloc = wid * 16 + (lane >> 2);
    #pragma unroll
    for (int nt = 0; nt < 16; nt++) {
        int c = nt * 8 + (lane & 3) * 2;
        *(float2*)&Ao[(size_t)rloc * E2_ + c] = make_float2(o[nt][0] * invA, o[nt][1] * invA);
        *(float2*)&Ao[(size_t)(rloc + 8) * E2_ + c] = make_float2(o[nt][2] * invB, o[nt][3] * invB);
    }
}

// ---------------- combine + layernorm + scale --------------------------------
__global__ void __launch_bounds__(128) final_kernel(const float* __restrict__ gamma,
                                                    const float* __restrict__ beta,
                                                    float* __restrict__ Out) {
    int h = blockIdx.x >> 11;
    int t = blockIdx.x & 2047;
    int e = threadIdx.x;
    size_t base = ((size_t)h * T_ + t) * E2_;
    float a1 = g_att1[base + e];
    float a2 = g_att2[base + e];
    float v = a1 - g_lam[h] * a2;

    float s1 = v, s2 = v * v;
    #pragma unroll
    for (int off = 16; off; off >>= 1) {
        s1 += __shfl_xor_sync(0xffffffffu, s1, off);
        s2 += __shfl_xor_sync(0xffffffffu, s2, off);
    }
    __shared__ float red[8];
    int w = e >> 5, lane = e & 31;
    if (lane == 0) { red[w] = s1; red[4 + w] = s2; }
    __syncthreads();
    float sum = red[0] + red[1] + red[2] + red[3];
    float sq  = red[4] + red[5] + red[6] + red[7];
    float mu  = sum * (1.f / 128.f);
    float var = fmaxf(sq * (1.f / 128.f) - mu * mu, 0.f);
    float nv  = (v - mu) * rsqrtf(var + EPS_);
    Out[base + e] = (nv * gamma[h * E2_ + e] + beta[h * E2_ + e]) * OUT_SCALE_;
}

// ---------------- launch -----------------------------------------------------
extern "C" void kernel_launch(void* const* d_in, const int* in_sizes, int n_in,
                              void* d_out, int out_size) {
    const float* x   = (const float*)d_in[0];
    const float* Wq  = (const float*)d_in[1];
    const float* Wk  = (const float*)d_in[2];
    const float* Wv  = (const float*)d_in[3];
    const float* Wqs = (const float*)d_in[4];
    const float* Wks = (const float*)d_in[5];
    const float* Wvs = (const float*)d_in[6];
    const float* lq1 = (const float*)d_in[7];
    const float* lq2 = (const float*)d_in[8];
    const float* lk1 = (const float*)d_in[9];
    const float* lk2 = (const float*)d_in[10];
    const float* gam = (const float*)d_in[11];
    const float* bet = (const float*)d_in[12];
    float* out = (float*)d_out;

    size_t psmem = 2 * PRJ_STAGEB;   // 81920
    cudaFuncSetAttribute(proj_mma, cudaFuncAttributeMaxDynamicSharedMemorySize, (int)psmem);
    cudaFuncSetAttribute(attn_kernel, cudaFuncAttributeMaxDynamicSharedMemorySize, AT_SMEM);

    lam_kernel<<<1, 32>>>(lq1, lq2, lk1, lk2);
    split_x<<<T_, 256>>>(x);
    transp_w<<<dim3(64, 4, 48), 256>>>(Wq, Wk, Wv);
    proj_mma<<<dim3(16, 16, 3), 256, psmem>>>();
    proj_fix<<<dim3(16, 3, 4), 128>>>(x, Wqs, Wks, Wvs);
    attn_kernel<<<512, 256, AT_SMEM>>>();
    final_kernel<<<32768, 128>>>(gam, bet, out);
}

// round 9
// speedup vs baseline: 3.9506x; 1.2367x over previous
#include <cuda_runtime.h>
#include <cuda_fp16.h>
#include <math.h>
#include <cstdint>

#define H_   16
#define T_   2048
#define DIM_ 2048
#define DK_  64
#define E2_  128
#define LAMBDA_INIT_ 0.6192834728526787f
#define OUT_SCALE_   0.3807165271473213f
#define EPS_ 1e-5f

// ---------------- scratch ----------------------------------------------------
__device__ float g_att1[H_*T_*E2_];
__device__ float g_att2[H_*T_*E2_];
__device__ float g_lam[H_];
__device__ __align__(256) __half g_xhi[T_*DIM_];
__device__ __align__(256) __half g_wthi[3*H_*E2_*DIM_];   // [sel][h][e][d]
__device__ __align__(256) __half g_wtlo[3*H_*E2_*DIM_];
__device__ __align__(256) __half g_qh[H_*T_*E2_];
__device__ __align__(256) __half g_ql[H_*T_*E2_];
__device__ __align__(256) __half g_kh[H_*T_*E2_];
__device__ __align__(256) __half g_kl[H_*T_*E2_];
__device__ __align__(256) __half g_vh[H_*T_*E2_];
__device__ __align__(256) __half g_vl[H_*T_*E2_];

// ---------------- helpers ----------------------------------------------------
__device__ __forceinline__ uint32_t smem_to_u32(const void* p) {
    uint32_t a;
    asm("{ .reg .u64 t; cvta.to.shared.u64 t, %1; cvt.u32.u64 %0, t; }" : "=r"(a) : "l"(p));
    return a;
}
#define LDSM4(r, addr) \
    asm volatile("ldmatrix.sync.aligned.m8n8.x4.shared.b16 {%0,%1,%2,%3}, [%4];" \
        : "=r"((r)[0]), "=r"((r)[1]), "=r"((r)[2]), "=r"((r)[3]) : "r"(addr))
#define LDSMT4(r, addr) \
    asm volatile("ldmatrix.sync.aligned.m8n8.x4.trans.shared.b16 {%0,%1,%2,%3}, [%4];" \
        : "=r"((r)[0]), "=r"((r)[1]), "=r"((r)[2]), "=r"((r)[3]) : "r"(addr))
#define MMA16816(c, a, b) \
    asm volatile("mma.sync.aligned.m16n8k16.row.col.f32.f16.f16.f32 " \
        "{%0,%1,%2,%3}, {%4,%5,%6,%7}, {%8,%9}, {%0,%1,%2,%3};" \
        : "+f"((c)[0]), "+f"((c)[1]), "+f"((c)[2]), "+f"((c)[3]) \
        : "r"((a)[0]), "r"((a)[1]), "r"((a)[2]), "r"((a)[3]), "r"((b)[0]), "r"((b)[1]))
#define CP_ASYNC16(sa, ga) \
    asm volatile("cp.async.cg.shared.global [%0], [%1], 16;" :: "r"(sa), "l"(ga))
#define CP_COMMIT() asm volatile("cp.async.commit_group;" ::: "memory")

__device__ __forceinline__ uint32_t packh2(__half a, __half b) {
    __half2 h = __halves2half2(a, b);
    return *(uint32_t*)&h;
}

// ---------------- lambda -----------------------------------------------------
__global__ void lam_kernel(const float* __restrict__ lq1, const float* __restrict__ lq2,
                           const float* __restrict__ lk1, const float* __restrict__ lk2) {
    int h = threadIdx.x;
    if (h < H_) {
        float d1 = 0.f, d2 = 0.f;
        for (int d = 0; d < DK_; d++) {
            d1 += lq1[h*DK_ + d] * lk1[h*DK_ + d];
            d2 += lq2[h*DK_ + d] * lk2[h*DK_ + d];
        }
        g_lam[h] = expf(d1) - expf(d2) + LAMBDA_INIT_;
    }
}

// ---------------- prep: X to fp16 (hi only) ----------------------------------
__global__ void __launch_bounds__(256) split_x(const float* __restrict__ X) {
    int t = blockIdx.x;
    const float* xp = X + (size_t)t * DIM_;
    __half* hp = g_xhi + (size_t)t * DIM_;
    for (int j = threadIdx.x; j < DIM_; j += 256)
        hp[j] = __float2half_rn(xp[j]);
}

// ---------------- prep: transpose + split W ----------------------------------
__global__ void __launch_bounds__(256) transp_w(const float* __restrict__ Wq,
                                                const float* __restrict__ Wk,
                                                const float* __restrict__ Wv) {
    __shared__ float tile[32][33];
    int hs = blockIdx.z;
    int sel = hs >> 4, h = hs & 15;
    const float* W = sel == 0 ? Wq : (sel == 1 ? Wk : Wv);
    int d0 = blockIdx.x * 32;
    int e0 = blockIdx.y * 32;
    int tx = threadIdx.x & 31, ty = threadIdx.x >> 5;
    #pragma unroll
    for (int i = 0; i < 4; i++) {
        int d = d0 + ty + i * 8;
        tile[ty + i * 8][tx] = W[((size_t)h * DIM_ + d) * E2_ + e0 + tx];
    }
    __syncthreads();
    #pragma unroll
    for (int i = 0; i < 4; i++) {
        int e = e0 + ty + i * 8;
        float v = tile[tx][ty + i * 8];
        __half hi = __float2half_rn(v);
        size_t idx = ((size_t)hs * E2_ + e) * DIM_ + d0 + tx;
        g_wthi[idx] = hi;
        g_wtlo[idx] = __float2half_rn(v - __half2float(hi));
    }
}

// ---------------- projection via mma.sync: Xhi*(Whi+Wlo) ---------------------
// K-chunk 64, 3 tiles/stage (Xhi,Whi,Wlo), 2 stages = 108KB -> 2 CTAs/SM.
#define PRJ_ROWB   144
#define PRJ_TILEB  (128*PRJ_ROWB)        // 18432
#define PRJ_STAGEB (3*PRJ_TILEB)         // 55296
#define PRJ_NSTG   32                    // 2048 / 64

__global__ void __launch_bounds__(256, 2) proj_mma() {
    extern __shared__ char smc[];
    uint32_t sbase = smem_to_u32(smc);
    int tid = threadIdx.x, lane = tid & 31, wid = tid >> 5;
    int tblk = blockIdx.x, h = blockIdx.y, sel = blockIdx.z;
    int row0 = tblk * 128;

    const char* gA0 = (const char*)g_xhi + (size_t)row0 * (DIM_ * 2);
    size_t wofs = (size_t)(sel * H_ + h) * E2_ * (DIM_ * 2);
    const char* gA1 = (const char*)g_wthi + wofs;
    const char* gA2 = (const char*)g_wtlo + wofs;

    int m0 = (wid >> 1) * 32, n0 = (wid & 1) * 64;
    float acc[2][8][4] = {};

    // issue one K-stage (64 k = 128B per row) into buffer b
    auto issue = [&](int s, int b) {
        uint32_t sb = sbase + b * PRJ_STAGEB;
        size_t k0b = (size_t)s * 128;
        #pragma unroll
        for (int i = 0; i < 4; i++) {
            int l = tid + i * 256;
            int row = l >> 3, seg = l & 7;
            size_t gofs = (size_t)row * (DIM_ * 2) + k0b + seg * 16;
            uint32_t sofs = row * PRJ_ROWB + seg * 16;
            CP_ASYNC16(sb + 0 * PRJ_TILEB + sofs, gA0 + gofs);
            CP_ASYNC16(sb + 1 * PRJ_TILEB + sofs, gA1 + gofs);
            CP_ASYNC16(sb + 2 * PRJ_TILEB + sofs, gA2 + gofs);
        }
        CP_COMMIT();
    };

    issue(0, 0);
    for (int s = 0; s < PRJ_NSTG; s++) {
        int b = s & 1;
        if (s < PRJ_NSTG - 1) issue(s + 1, b ^ 1);
        if (s < PRJ_NSTG - 1) asm volatile("cp.async.wait_group 1;" ::: "memory");
        else                  asm volatile("cp.async.wait_group 0;" ::: "memory");
        __syncthreads();

        uint32_t sA  = sbase + b * PRJ_STAGEB;
        uint32_t sBh = sA + PRJ_TILEB;
        uint32_t sBl = sBh + PRJ_TILEB;
        #pragma unroll
        for (int kk = 0; kk < 64; kk += 16) {
            uint32_t ah[2][4];
            #pragma unroll
            for (int mt = 0; mt < 2; mt++) {
                uint32_t off = (uint32_t)(m0 + mt * 16 + (lane & 15)) * PRJ_ROWB
                             + (kk + (lane >> 4) * 8) * 2;
                LDSM4(ah[mt], sA + off);
            }
            uint32_t bh[4][4], bl[4][4];
            #pragma unroll
            for (int np = 0; np < 4; np++) {
                uint32_t off = (uint32_t)(n0 + np * 16 + (lane & 7) + ((lane >> 4) & 1) * 8) * PRJ_ROWB
                             + (kk + ((lane >> 3) & 1) * 8) * 2;
                LDSM4(bh[np], sBh + off);
                LDSM4(bl[np], sBl + off);
            }
            #pragma unroll
            for (int mt = 0; mt < 2; mt++)
                #pragma unroll
                for (int nt = 0; nt < 8; nt++) {
                    uint32_t* bhp = &bh[nt >> 1][(nt & 1) * 2];
                    uint32_t* blp = &bl[nt >> 1][(nt & 1) * 2];
                    MMA16816(acc[mt][nt], ah[mt], bhp);
                    MMA16816(acc[mt][nt], ah[mt], blp);
                }
        }
        __syncthreads();
    }

    __half* Gh = (sel == 0 ? g_qh : (sel == 1 ? g_kh : g_vh)) + (size_t)h * T_ * E2_;
    __half* Gl = (sel == 0 ? g_ql : (sel == 1 ? g_kl : g_vl)) + (size_t)h * T_ * E2_;
    #pragma unroll
    for (int mt = 0; mt < 2; mt++)
        #pragma unroll
        for (int nt = 0; nt < 8; nt++) {
            int r = row0 + m0 + mt * 16 + (lane >> 2);
            int c = n0 + nt * 8 + (lane & 3) * 2;
            #pragma unroll
            for (int half2i = 0; half2i < 2; half2i++) {
                float v0 = acc[mt][nt][half2i * 2 + 0];
                float v1 = acc[mt][nt][half2i * 2 + 1];
                __half h0 = __float2half_rn(v0), h1 = __float2half_rn(v1);
                __half l0 = __float2half_rn(v0 - __half2float(h0));
                __half l1 = __float2half_rn(v1 - __half2float(h1));
                size_t o = (size_t)(r + half2i * 8) * E2_ + c;
                *(uint32_t*)&Gh[o] = packh2(h0, h1);
                *(uint32_t*)&Gl[o] = packh2(l0, l1);
            }
        }
}

// ---------------- fix-up: recompute 16 state rows with W_s (fp32) ------------
__global__ void __launch_bounds__(128) proj_fix(const float* __restrict__ X,
                                                const float* __restrict__ Wqs,
                                                const float* __restrict__ Wks,
                                                const float* __restrict__ Wvs) {
    __shared__ float xs[512][4];
    int h = blockIdx.x;
    int z = blockIdx.y;
    int g = blockIdx.z;
    const float* Ws = z == 0 ? Wqs : (z == 1 ? Wks : Wvs);
    __half* Gh = (z == 0 ? g_qh : (z == 1 ? g_kh : g_vh));
    __half* Gl = (z == 0 ? g_ql : (z == 1 ? g_kl : g_vl));
    int e = threadIdx.x;
    const float* Wp = Ws + (size_t)h * DIM_ * E2_ + e;
    float acc[4] = {};
    for (int d0 = 0; d0 < DIM_; d0 += 512) {
        __syncthreads();
        for (int l = threadIdx.x; l < 4 * 512; l += 128) {
            int ti = l >> 9;
            int c  = l & 511;
            int tok = g * 4 + ti;
            int t  = tok < 8 ? tok : 2032 + tok;
            xs[c][ti] = X[(size_t)t * DIM_ + d0 + c];
        }
        __syncthreads();
        for (int c = 0; c < 512; c++) {
            float w = Wp[(size_t)(d0 + c) * E2_];
            float4 x0 = *(const float4*)&xs[c][0];
            acc[0] = fmaf(x0.x, w, acc[0]);
            acc[1] = fmaf(x0.y, w, acc[1]);
            acc[2] = fmaf(x0.z, w, acc[2]);
            acc[3] = fmaf(x0.w, w, acc[3]);
        }
    }
    #pragma unroll
    for (int ti = 0; ti < 4; ti++) {
        int tok = g * 4 + ti;
        int t = tok < 8 ? tok : 2032 + tok;
        size_t idx = (size_t)h * T_ * E2_ + (size_t)t * E2_ + e;
        float v = acc[ti];
        __half hi = __float2half_rn(v);
        Gh[idx] = hi;
        Gl[idx] = __float2half_rn(v - __half2float(hi));
    }
}

// ---------------- flash attention via mma.sync -------------------------------
#define AT_ROWB  144
#define AT_VROWB 272
#define AT_QH    0
#define AT_QL    (128*AT_ROWB)
#define AT_ST0   (2*128*AT_ROWB)
#define AT_KH    0
#define AT_KL    (64*AT_ROWB)
#define AT_VH    (2*64*AT_ROWB)
#define AT_VL    (2*64*AT_ROWB + 64*AT_VROWB)
#define AT_STAGE (2*64*AT_ROWB + 2*64*AT_VROWB)
#define AT_SMEM  (AT_ST0 + 2*AT_STAGE)     // 143360

__global__ void __launch_bounds__(256) attn_kernel() {
    extern __shared__ char smc[];
    uint32_t sbase = smem_to_u32(smc);
    int tid = threadIdx.x, lane = tid & 31, wid = tid >> 5;
    int bid = (int)blockIdx.x;
    int qb = 15 - (bid >> 5);
    int rem = bid & 31;
    int h = rem >> 1;
    int which = rem & 1;
    int t0 = qb * 128;

    size_t hbase = (size_t)h * T_ * E2_;
    const char* Qh = (const char*)(g_qh + hbase + (size_t)t0 * E2_ + which * DK_);
    const char* Ql = (const char*)(g_ql + hbase + (size_t)t0 * E2_ + which * DK_);
    const char* Kh = (const char*)(g_kh + hbase + which * DK_);
    const char* Kl = (const char*)(g_kl + hbase + which * DK_);
    const char* Vh = (const char*)(g_vh + hbase);
    const char* Vl = (const char*)(g_vl + hbase);
    float* Ao = (which ? g_att2 : g_att1) + hbase + (size_t)t0 * E2_;

    #pragma unroll
    for (int i = 0; i < 4; i++) {
        int l = tid + i * 256;
        int row = l >> 3, seg = l & 7;
        uint32_t so = row * AT_ROWB + seg * 16;
        size_t go = (size_t)row * 256 + seg * 16;
        CP_ASYNC16(sbase + AT_QH + so, Qh + go);
        CP_ASYNC16(sbase + AT_QL + so, Ql + go);
    }
    CP_COMMIT();

    auto issue_kv = [&](int kb, int b) {
        uint32_t sb = sbase + AT_ST0 + b * AT_STAGE;
        size_t kofs = (size_t)kb * 64 * 256;
        #pragma unroll
        for (int i = 0; i < 2; i++) {
            int l = tid + i * 256;
            int row = l >> 3, seg = l & 7;
            uint32_t so = row * AT_ROWB + seg * 16;
            size_t go = kofs + (size_t)row * 256 + seg * 16;
            CP_ASYNC16(sb + AT_KH + so, Kh + go);
            CP_ASYNC16(sb + AT_KL + so, Kl + go);
        }
        #pragma unroll
        for (int i = 0; i < 4; i++) {
            int l = tid + i * 256;
            int row = l >> 4, seg = l & 15;
            uint32_t so = row * AT_VROWB + seg * 16;
            size_t go = kofs + (size_t)row * 256 + seg * 16;
            CP_ASYNC16(sb + AT_VH + so, Vh + go);
            CP_ASYNC16(sb + AT_VL + so, Vl + go);
        }
        CP_COMMIT();
    };

    issue_kv(0, 0);
    asm volatile("cp.async.wait_group 1;" ::: "memory");
    __syncthreads();

    uint32_t qh[4][4], ql[4][4];
    #pragma unroll
    for (int kt = 0; kt < 4; kt++) {
        uint32_t off = (uint32_t)(wid * 16 + (lane & 15)) * AT_ROWB
                     + (kt * 16 + (lane >> 4) * 8) * 2;
        LDSM4(qh[kt], sbase + AT_QH + off);
        LDSM4(ql[kt], sbase + AT_QL + off);
    }

    float o[16][4] = {};
    float mA = -INFINITY, mB = -INFINITY, lA = 0.f, lB = 0.f;
    int nkb = 2 * qb + 2;

    for (int kb = 0; kb < nkb; kb++) {
        int b = kb & 1;
        if (kb + 1 < nkb) {
            issue_kv(kb + 1, b ^ 1);
            asm volatile("cp.async.wait_group 1;" ::: "memory");
        } else {
            asm volatile("cp.async.wait_group 0;" ::: "memory");
        }
        __syncthreads();

        uint32_t sb = sbase + AT_ST0 + b * AT_STAGE;

        float s[8][4] = {};
        #pragma unroll
        for (int kt = 0; kt < 4; kt++) {
            uint32_t kfh[4][4], kfl[4][4];
            #pragma unroll
            for (int np = 0; np < 4; np++) {
                uint32_t off = (uint32_t)(np * 16 + (lane & 7) + ((lane >> 4) & 1) * 8) * AT_ROWB
                             + (kt * 16 + ((lane >> 3) & 1) * 8) * 2;
                LDSM4(kfh[np], sb + AT_KH + off);
                LDSM4(kfl[np], sb + AT_KL + off);
            }
            #pragma unroll
            for (int nt = 0; nt < 8; nt++) {
                uint32_t* bh = &kfh[nt >> 1][(nt & 1) * 2];
                uint32_t* bl = &kfl[nt >> 1][(nt & 1) * 2];
                MMA16816(s[nt], qh[kt], bh);
                MMA16816(s[nt], ql[kt], bh);
                MMA16816(s[nt], qh[kt], bl);
            }
        }

        bool diag = (kb >= 2 * qb);
        int rA = t0 + wid * 16 + (lane >> 2);
        #pragma unroll
        for (int nt = 0; nt < 8; nt++)
            #pragma unroll
            for (int e = 0; e < 4; e++) {
                float v = s[nt][e] * 0.125f;
                if (diag) {
                    int jc = kb * 64 + nt * 8 + (lane & 3) * 2 + (e & 1);
                    int ir = rA + (e >> 1) * 8;
                    if (jc > ir) v = -1e30f;
                }
                s[nt][e] = v;
            }

        float rmA = -INFINITY, rmB = -INFINITY;
        #pragma unroll
        for (int nt = 0; nt < 8; nt++) {
            rmA = fmaxf(rmA, fmaxf(s[nt][0], s[nt][1]));
            rmB = fmaxf(rmB, fmaxf(s[nt][2], s[nt][3]));
        }
        rmA = fmaxf(rmA, __shfl_xor_sync(0xffffffffu, rmA, 1));
        rmA = fmaxf(rmA, __shfl_xor_sync(0xffffffffu, rmA, 2));
        rmB = fmaxf(rmB, __shfl_xor_sync(0xffffffffu, rmB, 1));
        rmB = fmaxf(rmB, __shfl_xor_sync(0xffffffffu, rmB, 2));
        float nmA = fmaxf(mA, rmA), nmB = fmaxf(mB, rmB);
        float aA = __expf(mA - nmA), aB = __expf(mB - nmB);
        mA = nmA; mB = nmB;
        float rsA = 0.f, rsB = 0.f;
        #pragma unroll
        for (int nt = 0; nt < 8; nt++) {
            s[nt][0] = __expf(s[nt][0] - nmA);
            s[nt][1] = __expf(s[nt][1] - nmA);
            s[nt][2] = __expf(s[nt][2] - nmB);
            s[nt][3] = __expf(s[nt][3] - nmB);
            rsA += s[nt][0] + s[nt][1];
            rsB += s[nt][2] + s[nt][3];
        }
        rsA += __shfl_xor_sync(0xffffffffu, rsA, 1);
        rsA += __shfl_xor_sync(0xffffffffu, rsA, 2);
        rsB += __shfl_xor_sync(0xffffffffu, rsB, 1);
        rsB += __shfl_xor_sync(0xffffffffu, rsB, 2);
        lA = lA * aA + rsA;
        lB = lB * aB + rsB;
        #pragma unroll
        for (int nt = 0; nt < 16; nt++) {
            o[nt][0] *= aA; o[nt][1] *= aA;
            o[nt][2] *= aB; o[nt][3] *= aB;
        }

        uint32_t ph[4][4], pl[4][4];
        #pragma unroll
        for (int kt = 0; kt < 4; kt++)
            #pragma unroll
            for (int half16 = 0; half16 < 2; half16++) {
                float* e = s[2 * kt + half16];
                __half h0 = __float2half_rn(e[0]), h1 = __float2half_rn(e[1]);
                __half h2 = __float2half_rn(e[2]), h3 = __float2half_rn(e[3]);
                ph[kt][half16 * 2 + 0] = packh2(h0, h1);
                ph[kt][half16 * 2 + 1] = packh2(h2, h3);
                pl[kt][half16 * 2 + 0] = packh2(__float2half_rn(e[0] - __half2float(h0)),
                                                __float2half_rn(e[1] - __half2float(h1)));
                pl[kt][half16 * 2 + 1] = packh2(__float2half_rn(e[2] - __half2float(h2)),
                                                __float2half_rn(e[3] - __half2float(h3)));
            }

        #pragma unroll
        for (int kt = 0; kt < 4; kt++) {
            #pragma unroll
            for (int vn = 0; vn < 8; vn++) {
                uint32_t off = (uint32_t)(kt * 16 + (lane & 15)) * AT_VROWB
                             + (vn * 16 + (lane >> 4) * 8) * 2;
                uint32_t vf[4], vg[4];
                LDSMT4(vf, sb + AT_VH + off);
                LDSMT4(vg, sb + AT_VL + off);
                MMA16816(o[2 * vn + 0], ph[kt], &vf[0]);
                MMA16816(o[2 * vn + 0], pl[kt], &vf[0]);
                MMA16816(o[2 * vn + 0], ph[kt], &vg[0]);
                MMA16816(o[2 * vn + 1], ph[kt], &vf[2]);
                MMA16816(o[2 * vn + 1], pl[kt], &vf[2]);
                MMA16816(o[2 * vn + 1], ph[kt], &vg[2]);
            }
        }
        __syncthreads();
    }

    float invA = 1.f / lA, invB = 1.f / lB;
    int rloc = wid * 16 + (lane >> 2);
    #pragma unroll
    for (int nt = 0; nt < 16; nt++) {
        int c = nt * 8 + (lane & 3) * 2;
        *(float2*)&Ao[(size_t)rloc * E2_ + c] = make_float2(o[nt][0] * invA, o[nt][1] * invA);
        *(float2*)&Ao[(size_t)(rloc + 8) * E2_ + c] = make_float2(o[nt][2] * invB, o[nt][3] * invB);
    }
}

// ---------------- combine + layernorm + scale --------------------------------
__global__ void __launch_bounds__(128) final_kernel(const float* __restrict__ gamma,
                                                    const float* __restrict__ beta,
                                                    float* __restrict__ Out) {
    int h = blockIdx.x >> 11;
    int t = blockIdx.x & 2047;
    int e = threadIdx.x;
    size_t base = ((size_t)h * T_ + t) * E2_;
    float a1 = g_att1[base + e];
    float a2 = g_att2[base + e];
    float v = a1 - g_lam[h] * a2;

    float s1 = v, s2 = v * v;
    #pragma unroll
    for (int off = 16; off; off >>= 1) {
        s1 += __shfl_xor_sync(0xffffffffu, s1, off);
        s2 += __shfl_xor_sync(0xffffffffu, s2, off);
    }
    __shared__ float red[8];
    int w = e >> 5, lane = e & 31;
    if (lane == 0) { red[w] = s1; red[4 + w] = s2; }
    __syncthreads();
    float sum = red[0] + red[1] + red[2] + red[3];
    float sq  = red[4] + red[5] + red[6] + red[7];
    float mu  = sum * (1.f / 128.f);
    float var = fmaxf(sq * (1.f / 128.f) - mu * mu, 0.f);
    float nv  = (v - mu) * rsqrtf(var + EPS_);
    Out[base + e] = (nv * gamma[h * E2_ + e] + beta[h * E2_ + e]) * OUT_SCALE_;
}

// ---------------- launch -----------------------------------------------------
extern "C" void kernel_launch(void* const* d_in, const int* in_sizes, int n_in,
                              void* d_out, int out_size) {
    const float* x   = (const float*)d_in[0];
    const float* Wq  = (const float*)d_in[1];
    const float* Wk  = (const float*)d_in[2];
    const float* Wv  = (const float*)d_in[3];
    const float* Wqs = (const float*)d_in[4];
    const float* Wks = (const float*)d_in[5];
    const float* Wvs = (const float*)d_in[6];
    const float* lq1 = (const float*)d_in[7];
    const float* lq2 = (const float*)d_in[8];
    const float* lk1 = (const float*)d_in[9];
    const float* lk2 = (const float*)d_in[10];
    const float* gam = (const float*)d_in[11];
    const float* bet = (const float*)d_in[12];
    float* out = (float*)d_out;

    size_t psmem = 2 * PRJ_STAGEB;   // 110592
    cudaFuncSetAttribute(proj_mma, cudaFuncAttributeMaxDynamicSharedMemorySize, (int)psmem);
    cudaFuncSetAttribute(attn_kernel, cudaFuncAttributeMaxDynamicSharedMemorySize, AT_SMEM);

    lam_kernel<<<1, 32>>>(lq1, lq2, lk1, lk2);
    split_x<<<T_, 256>>>(x);
    transp_w<<<dim3(64, 4, 48), 256>>>(Wq, Wk, Wv);
    proj_mma<<<dim3(16, 16, 3), 256, psmem>>>();
    proj_fix<<<dim3(16, 3, 4), 128>>>(x, Wqs, Wks, Wvs);
    attn_kernel<<<512, 256, AT_SMEM>>>();
    final_kernel<<<32768, 128>>>(gam, bet, out);
}